// round 5
// baseline (speedup 1.0000x reference)
#include <cuda_runtime.h>
#include <mma.h>
#include <cstdint>
#include <cstddef>

using namespace nvcuda;

// ---------------- problem constants ----------------
#define BATCH   32
#define SEQL    576                 // 24*24 tokens
#define MTOK    (BATCH*SEQL)        // 18432
#define DIMV    192
#define DIN     384                 // 2*DIM
#define DSTATE  16
#define DTRANK  12
#define NPROJP  64                  // padded proj row stride (real cols: 44)
#define KPATCH  768                 // 3*16*16

// ---------------- scratch (device globals; no allocation) ----------------
__device__ float g_xcol[(size_t)MTOK * KPATCH];           // 56.6 MB
__device__ float g_tok [(size_t)MTOK * DIMV];             // 14.2 MB
__device__ float g_xz  [2][(size_t)MTOK * 2*DIN];         // 113 MB
__device__ float g_xc  [2][(size_t)MTOK * DIN];           // 56.6 MB
__device__ float g_proj[2][(size_t)MTOK * NPROJP];        // 9.4 MB
__device__ float g_dt  [2][(size_t)MTOK * DIN];           // 56.6 MB
__device__ float g_ysum[2][BATCH * DIN];

// ---------------- FMA-pipe transcendentals ----------------
__device__ __forceinline__ float fexp(float x) {
    x = fminf(fmaxf(x, -87.0f), 87.0f);
    float t  = fmaf(x, 1.4426950408889634f, 12582912.0f);
    int   ni = __float_as_int(t) - 0x4B400000;
    float n  = t - 12582912.0f;
    float f  = fmaf(x, 1.4426950408889634f, -n);
    float p  =              1.5252733804059840e-05f;
    p = fmaf(p, f, 1.5403530393381609e-04f);
    p = fmaf(p, f, 1.3333558146428443e-03f);
    p = fmaf(p, f, 9.6181291076284772e-03f);
    p = fmaf(p, f, 5.5504108664821576e-02f);
    p = fmaf(p, f, 2.4022650695910071e-01f);
    p = fmaf(p, f, 6.9314718055994531e-01f);
    p = fmaf(p, f, 1.0f);
    return __int_as_float((ni << 23) + __float_as_int(p));
}

__device__ __forceinline__ float frcp(float w) {            // w > 0
    float r = __int_as_float(0x7EF311C3 - __float_as_int(w));
    r = r * fmaf(-w, r, 2.0f);
    r = r * fmaf(-w, r, 2.0f);
    r = r * fmaf(-w, r, 2.0f);
    return r;
}

__device__ __forceinline__ float fsilu(float x) {
    return x * frcp(1.0f + fexp(-x));
}

__device__ __forceinline__ float fsoftplus(float x) {
    float u  = fexp(-fabsf(x));
    float s  = u * frcp(u + 2.0f);
    float s2 = s * s;
    float p  = 1.0f/11.0f;
    p = fmaf(p, s2, 1.0f/9.0f);
    p = fmaf(p, s2, 1.0f/7.0f);
    p = fmaf(p, s2, 1.0f/5.0f);
    p = fmaf(p, s2, 1.0f/3.0f);
    p = fmaf(p, s2, 1.0f);
    return fmaxf(x, 0.0f) + 2.0f * s * p;
}

// ---------------- im2col for patch embed ----------------
__global__ void im2col_kernel(const float* __restrict__ x) {
    int i = blockIdx.x * 256 + threadIdx.x;
    if (i >= MTOK * KPATCH) return;
    int row = i / KPATCH, col = i - row * KPATCH;
    int b  = row / SEQL;  int rl = row - b * SEQL;
    int hp = rl / 24,     wp = rl - hp * 24;
    int c  = col >> 8;    int cr = col & 255;
    int p  = cr >> 4,     q  = cr & 15;
    g_xcol[i] = x[((size_t)(b*3 + c)*384 + hp*16 + p)*384 + (wp*16 + q)];
}

// ---------------- tf32 WMMA GEMM, double-buffered ---------------------------
// C[M,Nout] = A[M,K] @ W[Nw,K]^T  (rows of W beyond Nw treated as zero).
// Block tile 256x64x32, 256 threads = 8 warps (4m x 2n), warp tile 64x32
// (4x2 wmma m16n16k8). Requires M%256==0, Nout%64 (per grid), K%32==0.
// tf32 rounding applied at smem store; inner loop is pure ld/mma.
#define GLDW 36                       // padded smem row (floats)
#define GA_STRIDE (256*GLDW)
#define GB_STRIDE (64*GLDW)
#define GEMM_SMEM ((2*GA_STRIDE + 2*GB_STRIDE)*4)

__global__ __launch_bounds__(256, 2) void gemm_tf32_kernel(
    const float* __restrict__ A, const float* __restrict__ W,
    float* __restrict__ C, int K, int Nw, int Nout)
{
    extern __shared__ float sm[];
    float* As = sm;                    // [2][256][GLDW]
    float* Bs = sm + 2*GA_STRIDE;      // [2][64][GLDW]
    const int tid  = threadIdx.x;
    const int warp = tid >> 5;
    const int wm   = warp >> 1;        // 0..3
    const int wn   = warp & 1;         // 0..1
    const int m0 = blockIdx.y * 256;
    const int n0 = blockIdx.x * 64;
    const int ar = tid >> 3, akc = (tid & 7) * 4;   // per-thread tile coords

    wmma::fragment<wmma::accumulator,16,16,8,float> acc[4][2];
    #pragma unroll
    for (int i = 0; i < 4; i++)
        #pragma unroll
        for (int j = 0; j < 2; j++)
            wmma::fill_fragment(acc[i][j], 0.0f);

    float4 pa[8], pb[2];

    #define LOAD_TILES(k0)  do {                                              \
        _Pragma("unroll")                                                     \
        for (int i = 0; i < 8; i++)                                           \
            pa[i] = *(const float4*)&A[(size_t)(m0 + ar + i*32)*K + (k0) + akc]; \
        _Pragma("unroll")                                                     \
        for (int i = 0; i < 2; i++) {                                         \
            int r = ar + i*32;                                                \
            pb[i] = (n0 + r < Nw)                                             \
                ? *(const float4*)&W[(size_t)(n0 + r)*K + (k0) + akc]         \
                : make_float4(0.f,0.f,0.f,0.f);                               \
        }                                                                     \
    } while (0)

    #define STORE_TILES(buf)  do {                                           \
        _Pragma("unroll")                                                     \
        for (int i = 0; i < 8; i++) {                                         \
            float* p = &As[(buf)*GA_STRIDE + (ar + i*32)*GLDW + akc];         \
            p[0] = wmma::__float_to_tf32(pa[i].x);                            \
            p[1] = wmma::__float_to_tf32(pa[i].y);                            \
            p[2] = wmma::__float_to_tf32(pa[i].z);                            \
            p[3] = wmma::__float_to_tf32(pa[i].w);                            \
        }                                                                     \
        _Pragma("unroll")                                                     \
        for (int i = 0; i < 2; i++) {                                         \
            float* p = &Bs[(buf)*GB_STRIDE + (ar + i*32)*GLDW + akc];         \
            p[0] = wmma::__float_to_tf32(pb[i].x);                            \
            p[1] = wmma::__float_to_tf32(pb[i].y);                            \
            p[2] = wmma::__float_to_tf32(pb[i].z);                            \
            p[3] = wmma::__float_to_tf32(pb[i].w);                            \
        }                                                                     \
    } while (0)

    LOAD_TILES(0);
    STORE_TILES(0);
    __syncthreads();

    int buf = 0;
    for (int k0 = 0; k0 < K; k0 += 32) {
        const bool more = (k0 + 32) < K;
        if (more) LOAD_TILES(k0 + 32);
        // compute on current stage
        #pragma unroll
        for (int kk = 0; kk < 32; kk += 8) {
            wmma::fragment<wmma::matrix_b,16,16,8,wmma::precision::tf32,wmma::col_major> bf[2];
            #pragma unroll
            for (int j = 0; j < 2; j++)
                wmma::load_matrix_sync(bf[j],
                    &Bs[buf*GB_STRIDE + (wn*32 + j*16)*GLDW + kk], GLDW);
            #pragma unroll
            for (int i = 0; i < 4; i++) {
                wmma::fragment<wmma::matrix_a,16,16,8,wmma::precision::tf32,wmma::row_major> af;
                wmma::load_matrix_sync(af,
                    &As[buf*GA_STRIDE + (wm*64 + i*16)*GLDW + kk], GLDW);
                #pragma unroll
                for (int j = 0; j < 2; j++)
                    wmma::mma_sync(acc[i][j], af, bf[j], acc[i][j]);
            }
        }
        if (more) STORE_TILES(buf ^ 1);
        __syncthreads();
        buf ^= 1;
    }

    #pragma unroll
    for (int i = 0; i < 4; i++)
        #pragma unroll
        for (int j = 0; j < 2; j++)
            wmma::store_matrix_sync(
                &C[(size_t)(m0 + wm*64 + i*16)*Nout + n0 + wn*32 + j*16],
                acc[i][j], Nout, wmma::mem_row_major);
    #undef LOAD_TILES
    #undef STORE_TILES
}

// ---------------- LayerNorm over DIM=192 (patch bias folded in) -------------
__global__ void ln_kernel(float* __restrict__ tok, const float* __restrict__ pb,
                          const float* __restrict__ g, const float* __restrict__ b) {
    int row  = blockIdx.x * 8 + (threadIdx.x >> 5);
    int lane = threadIdx.x & 31;
    float* p = tok + (size_t)row * DIMV;
    float v[6]; float s = 0.f;
    #pragma unroll
    for (int i = 0; i < 6; i++) {
        int c = lane + i*32;
        v[i] = p[c] + pb[c];
        s += v[i];
    }
    #pragma unroll
    for (int o = 16; o; o >>= 1) s += __shfl_xor_sync(0xffffffffu, s, o);
    float mu = s * (1.0f/192.0f);
    float q = 0.f;
    #pragma unroll
    for (int i = 0; i < 6; i++) { float d = v[i] - mu; q = fmaf(d, d, q); }
    #pragma unroll
    for (int o = 16; o; o >>= 1) q += __shfl_xor_sync(0xffffffffu, q, o);
    float rstd = rsqrtf(q * (1.0f/192.0f) + 1e-5f);
    #pragma unroll
    for (int i = 0; i < 6; i++) {
        int c = lane + i*32;
        p[c] = (v[i] - mu) * rstd * g[c] + b[c];
    }
}

// ---------------- depthwise causal/anticausal conv + silu -------------------
__global__ void conv_silu_kernel(const float* __restrict__ cwf, const float* __restrict__ cbf,
                                 const float* __restrict__ cwb, const float* __restrict__ cbb) {
    int dir = blockIdx.y;
    int i = blockIdx.x * 256 + threadIdx.x;            // over MTOK*DIN
    if (i >= MTOK * DIN) return;
    int r = i / DIN, d = i - r * DIN;
    int b = r / SEQL, l = r - b * SEQL;
    const float* xz = g_xz[dir];
    const float* cw = dir ? cwb : cwf;
    const float* cb = dir ? cbb : cbf;
    float acc = cb[d];
    #pragma unroll
    for (int k = 0; k < 4; k++) {
        int ll = dir ? (l + 3 - k) : (l - 3 + k);
        if (ll >= 0 && ll < SEQL)
            acc = fmaf(xz[((size_t)(b*SEQL + ll))*(2*DIN) + d], cw[d*4 + k], acc);
    }
    g_xc[dir][i] = fsilu(acc);
}

// ---------------- dt = softplus(dt_raw @ dt_w^T + dt_b), K=12 ---------------
__global__ void dt_kernel(const float* __restrict__ wf, const float* __restrict__ bf,
                          const float* __restrict__ wb, const float* __restrict__ bb) {
    int dir = blockIdx.y;
    int r0 = blockIdx.x * 16;
    int d = threadIdx.x;                               // 384
    __shared__ float dtr[16][12];
    if (threadIdx.x < 192) {
        int rr = threadIdx.x / 12, k = threadIdx.x - rr*12;
        dtr[rr][k] = g_proj[dir][(size_t)(r0 + rr)*NPROJP + k];
    }
    const float* w = dir ? wb : wf;
    float wreg[12];
    #pragma unroll
    for (int k = 0; k < 12; k++) wreg[k] = w[d*12 + k];
    float bias = (dir ? bb : bf)[d];
    __syncthreads();
    #pragma unroll 4
    for (int rr = 0; rr < 16; rr++) {
        float acc = bias;
        #pragma unroll
        for (int k = 0; k < 12; k++) acc = fmaf(dtr[rr][k], wreg[k], acc);
        g_dt[dir][(size_t)(r0 + rr)*DIN + d] = fsoftplus(acc);
    }
}

// ---------------- selective scan; accumulates sum over L directly ----------
__global__ __launch_bounds__(128) void scan_kernel(
    const float* __restrict__ Alf, const float* __restrict__ Df,
    const float* __restrict__ Alb, const float* __restrict__ Db)
{
    int gid  = (blockIdx.x * 128 + threadIdx.x) >> 2;
    int lane = threadIdx.x & 3;
    if (gid >= 2 * BATCH * DIN) return;
    int dir = gid >= BATCH * DIN;
    int rem = gid - dir * BATCH * DIN;
    int b = rem / DIN, d = rem - b * DIN;
    const float* Alog = dir ? Alb : Alf;
    float Dv = (dir ? Db : Df)[d];
    float a0 = -fexp(Alog[d*DSTATE + lane*4 + 0]);
    float a1 = -fexp(Alog[d*DSTATE + lane*4 + 1]);
    float a2 = -fexp(Alog[d*DSTATE + lane*4 + 2]);
    float a3 = -fexp(Alog[d*DSTATE + lane*4 + 3]);
    const float* dtp = g_dt[dir];
    const float* xcp = g_xc[dir];
    const float* zp  = g_xz[dir];                      // z at [r*2*DIN + DIN + d]
    const float* pp  = g_proj[dir];
    float h0=0.f,h1=0.f,h2=0.f,h3=0.f, acc=0.f;
    int r    = b*SEQL + (dir ? SEQL - 1 : 0);
    int step = dir ? -1 : 1;

    size_t rd = (size_t)r * DIN + d;
    float dtv = dtp[rd], xcv = xcp[rd];
    float zv  = zp[(size_t)r*(2*DIN) + DIN + d];
    float4 Bv = *(const float4*)&pp[(size_t)r*NPROJP + DTRANK + lane*4];
    float4 Cv = *(const float4*)&pp[(size_t)r*NPROJP + DTRANK + DSTATE + lane*4];

    for (int t = 0; t < SEQL; t++) {
        int rn = r + step;
        float ndt = 0.f, nxc = 0.f, nz = 0.f;
        float4 nB = Bv, nC = Cv;
        if (t + 1 < SEQL) {
            size_t rdn = (size_t)rn * DIN + d;
            ndt = dtp[rdn]; nxc = xcp[rdn];
            nz  = zp[(size_t)rn*(2*DIN) + DIN + d];
            nB = *(const float4*)&pp[(size_t)rn*NPROJP + DTRANK + lane*4];
            nC = *(const float4*)&pp[(size_t)rn*NPROJP + DTRANK + DSTATE + lane*4];
        }
        float dtx = dtv * xcv;
        h0 = fmaf(fexp(dtv*a0), h0, dtx*Bv.x);
        h1 = fmaf(fexp(dtv*a1), h1, dtx*Bv.y);
        h2 = fmaf(fexp(dtv*a2), h2, dtx*Bv.z);
        h3 = fmaf(fexp(dtv*a3), h3, dtx*Bv.w);
        float part = fmaf(h0,Cv.x, fmaf(h1,Cv.y, fmaf(h2,Cv.z, h3*Cv.w)));
        part += __shfl_xor_sync(0xffffffffu, part, 1);
        part += __shfl_xor_sync(0xffffffffu, part, 2);
        acc = fmaf(fmaf(xcv, Dv, part), fsilu(zv), acc);
        dtv = ndt; xcv = nxc; zv = nz; Bv = nB; Cv = nC; r = rn;
    }
    if (lane == 0) g_ysum[dir][b*DIN + d] = acc;
}

// ---------------- head: mean -> out_proj (both dirs) -> fc ------------------
__global__ void head_kernel(const float* __restrict__ fow, const float* __restrict__ bow,
                            const float* __restrict__ fcw, const float* __restrict__ fcb,
                            float* __restrict__ out) {
    int b = blockIdx.x;
    __shared__ float ys0[DIN], ys1[DIN], o[DIMV];
    int t = threadIdx.x;                               // 192
    for (int i = t; i < DIN; i += DIMV) {
        ys0[i] = g_ysum[0][b*DIN + i] * (1.0f/SEQL);
        ys1[i] = g_ysum[1][b*DIN + i] * (1.0f/SEQL);
    }
    __syncthreads();
    float acc = 0.f;
    #pragma unroll 4
    for (int di = 0; di < DIN; di++)
        acc = fmaf(ys0[di], fow[(size_t)t*DIN + di], fmaf(ys1[di], bow[(size_t)t*DIN + di], acc));
    o[t] = acc;
    __syncthreads();
    if (t < 4) {
        float s = fcb[t];
        #pragma unroll 4
        for (int d = 0; d < DIMV; d++) s = fmaf(o[d], fcw[t*DIMV + d], s);
        out[b*4 + t] = s;
    }
}

// ---------------- launch ----------------------------------------------------
extern "C" void kernel_launch(void* const* d_in, const int* in_sizes, int n_in,
                              void* d_out, int out_size) {
    (void)in_sizes; (void)n_in; (void)out_size;
    const float* x       = (const float*)d_in[0];
    const float* patch_w = (const float*)d_in[1];
    const float* patch_b = (const float*)d_in[2];
    const float* ln_g    = (const float*)d_in[3];
    const float* ln_b    = (const float*)d_in[4];
    const float* fc_w    = (const float*)d_in[5];
    const float* fc_b    = (const float*)d_in[6];
    // per-direction params: in_w, conv_w, conv_b, xproj_w, dt_w, dt_b, A_log, D, out_w
    const float* P[2][9];
    for (int dir = 0; dir < 2; dir++)
        for (int i = 0; i < 9; i++)
            P[dir][i] = (const float*)d_in[7 + dir*9 + i];

    float *xcol, *tok, *xz, *xc, *proj;
    cudaGetSymbolAddress((void**)&xcol, g_xcol);
    cudaGetSymbolAddress((void**)&tok,  g_tok);
    cudaGetSymbolAddress((void**)&xz,   g_xz);
    cudaGetSymbolAddress((void**)&xc,   g_xc);
    cudaGetSymbolAddress((void**)&proj, g_proj);

    static bool attr_done = false;
    if (!attr_done) {
        cudaFuncSetAttribute(gemm_tf32_kernel,
                             cudaFuncAttributeMaxDynamicSharedMemorySize, GEMM_SMEM);
        attr_done = true;
    }

    // 1. im2col
    im2col_kernel<<<(MTOK*KPATCH + 255)/256, 256>>>(x);
    // 2. patch embed GEMM (tf32) -> tok (bias folded into LN)
    gemm_tf32_kernel<<<dim3(DIMV/64, MTOK/256), 256, GEMM_SMEM>>>(
        xcol, patch_w, tok, KPATCH, DIMV, DIMV);
    // 3. layernorm in place (adds patch_b first)
    ln_kernel<<<MTOK/8, 256>>>(tok, patch_b, ln_g, ln_b);
    // 4. in-projection per direction (tf32)
    for (int dir = 0; dir < 2; dir++)
        gemm_tf32_kernel<<<dim3((2*DIN)/64, MTOK/256), 256, GEMM_SMEM>>>(
            tok, P[dir][0], xz + (size_t)dir*MTOK*2*DIN, DIMV, 2*DIN, 2*DIN);
    // 5. conv + silu
    conv_silu_kernel<<<dim3((MTOK*DIN)/256, 2), 256>>>(P[0][1], P[0][2], P[1][1], P[1][2]);
    // 6. x-projection (dt_raw | B | C), weights zero-padded 44 -> 64 cols
    for (int dir = 0; dir < 2; dir++)
        gemm_tf32_kernel<<<dim3(1, MTOK/256), 256, GEMM_SMEM>>>(
            xc + (size_t)dir*MTOK*DIN, P[dir][3],
            proj + (size_t)dir*MTOK*NPROJP, DIN, 44, NPROJP);
    // 7. dt projection + softplus
    dt_kernel<<<dim3(MTOK/16, 2), 384>>>(P[0][4], P[0][5], P[1][4], P[1][5]);
    // 8. selective scan (both directions), accumulating token-sum
    scan_kernel<<<(2*BATCH*DIN*4)/128, 128>>>(P[0][6], P[0][7], P[1][6], P[1][7]);
    // 9. head: mean-pool -> out_w (both dirs) -> fc
    head_kernel<<<BATCH, DIMV>>>(P[0][8], P[1][8], fc_w, fc_b, (float*)d_out);
}

// round 7
// speedup vs baseline: 1.4663x; 1.4663x over previous
#include <cuda_runtime.h>
#include <cuda_bf16.h>
#include <mma.h>
#include <cstdint>
#include <cstddef>

using namespace nvcuda;

// ---------------- problem constants ----------------
#define BATCH   32
#define SEQL    576                 // 24*24 tokens
#define MTOK    (BATCH*SEQL)        // 18432
#define DIMV    192
#define DIN     384                 // 2*DIM
#define DSTATE  16
#define DTRANK  12
#define NPROJP  64                  // padded proj row stride (real cols: 44)

// ---------------- scratch (device globals; no allocation) ----------------
__device__ float g_tok [(size_t)MTOK * DIMV];             // 14.2 MB
__device__ float g_xz  [2][(size_t)MTOK * 2*DIN];         // 113 MB
__device__ float g_xc  [2][(size_t)MTOK * DIN];           // 56.6 MB
__device__ float g_proj[2][(size_t)MTOK * NPROJP];        // 9.4 MB
__device__ float g_dt  [2][(size_t)MTOK * DIN];           // 56.6 MB
__device__ float g_ysum[2][BATCH * DIN];

// ---------------- bf16-split (error-compensated) WMMA GEMM ------------------
// C[M,Nout] = A[M,K] @ W[Nw,K]^T, rows of W beyond Nw are zero.
// A = hi + lo (bf16 each); acc += Ah*Bh + Al*Bh + Ah*Bl gives ~2^-17 relative
// accuracy at bf16-MMA speed with ldmatrix fragment loads.
// Block tile 128x64x32, 8 warps (4m x 2n), warp tile 32x32 = 2x2 wmma
// m16n16k16 per 16-wide kk step. Double-buffered smem.
// blockIdx.z selects (A,W,C) set 0 or 1 for fused dual-direction launches.
// IMC: implicit im2col of x[32,3,384,384] into A[MTOK, 768] (16x16 patches).
#define MT 128
#define NT 64
#define KT 32
#define SBK 40                      // smem row stride in bf16 elems (pad 32->40)
#define ASZ (MT*SBK)                // 5120 elems per stage
#define BSZ (NT*SBK)                // 2560
#define GEMM_SMEM ((4*ASZ + 4*BSZ) * 2)   // bytes = 61440

#define CVTSTORE(dsthi, dstlo, off, v) do {                                   \
    __nv_bfloat162 h0_ = __floats2bfloat162_rn((v).x, (v).y);                 \
    __nv_bfloat162 h1_ = __floats2bfloat162_rn((v).z, (v).w);                 \
    __nv_bfloat162 l0_ = __floats2bfloat162_rn((v).x - __low2float(h0_),      \
                                               (v).y - __high2float(h0_));    \
    __nv_bfloat162 l1_ = __floats2bfloat162_rn((v).z - __low2float(h1_),      \
                                               (v).w - __high2float(h1_));    \
    *(__nv_bfloat162*)&(dsthi)[(off)]     = h0_;                              \
    *(__nv_bfloat162*)&(dsthi)[(off) + 2] = h1_;                              \
    *(__nv_bfloat162*)&(dstlo)[(off)]     = l0_;                              \
    *(__nv_bfloat162*)&(dstlo)[(off) + 2] = l1_;                              \
} while (0)

template<bool IMC>
__global__ __launch_bounds__(256, 2) void gemm_bfs_kernel(
    const float* __restrict__ A0, const float* __restrict__ A1,
    const float* __restrict__ W0, const float* __restrict__ W1,
    float* __restrict__ C0, float* __restrict__ C1,
    int K, int Nw, int Nout)
{
    extern __shared__ __nv_bfloat16 sm[];
    __nv_bfloat16* Ahi = sm;                    // [2][MT][SBK]
    __nv_bfloat16* Alo = sm + 2*ASZ;
    __nv_bfloat16* Bhi = sm + 4*ASZ;            // [2][NT][SBK]
    __nv_bfloat16* Blo = sm + 4*ASZ + 2*BSZ;

    const float* A = blockIdx.z ? A1 : A0;
    const float* W = blockIdx.z ? W1 : W0;
    float*       C = blockIdx.z ? C1 : C0;

    const int tid  = threadIdx.x;
    const int warp = tid >> 5;
    const int wm   = warp >> 1;      // 0..3 -> m offset wm*32
    const int wn   = warp & 1;       // 0..1 -> n offset wn*32
    const int m0 = blockIdx.y * MT;
    const int n0 = blockIdx.x * NT;
    const int ar = tid >> 3, akc = (tid & 7) * 4;

    int rb[4];
    if (IMC) {
        #pragma unroll
        for (int i = 0; i < 4; i++) {
            int tok = m0 + ar + i*32;
            int b = tok / SEQL, rl = tok - b*SEQL;
            int hp = rl / 24, wp = rl - hp*24;
            rb[i] = b*442368 + hp*6144 + wp*16;   // 3*384*384, 16*384
        }
    }

    wmma::fragment<wmma::accumulator,16,16,16,float> acc[2][2];
    #pragma unroll
    for (int i = 0; i < 2; i++)
        #pragma unroll
        for (int j = 0; j < 2; j++)
            wmma::fill_fragment(acc[i][j], 0.0f);

    float4 pa[4], pb[2];

    #define LOADT(k0)  do {                                                   \
        if (IMC) {                                                            \
            int k_ = (k0) + akc;                                              \
            int c_ = k_ >> 8, pq_ = k_ & 255;                                 \
            int koff_ = c_*147456 + (pq_ >> 4)*384 + (pq_ & 15);              \
            _Pragma("unroll")                                                 \
            for (int i = 0; i < 4; i++)                                       \
                pa[i] = *(const float4*)&A[rb[i] + koff_];                    \
        } else {                                                              \
            _Pragma("unroll")                                                 \
            for (int i = 0; i < 4; i++)                                       \
                pa[i] = *(const float4*)&A[(size_t)(m0 + ar + i*32)*K + (k0) + akc]; \
        }                                                                     \
        _Pragma("unroll")                                                     \
        for (int i = 0; i < 2; i++) {                                         \
            int r_ = ar + i*32;                                               \
            pb[i] = (n0 + r_ < Nw)                                            \
                ? *(const float4*)&W[(size_t)(n0 + r_)*K + (k0) + akc]        \
                : make_float4(0.f,0.f,0.f,0.f);                               \
        }                                                                     \
    } while (0)

    #define STORET(buf)  do {                                                 \
        _Pragma("unroll")                                                     \
        for (int i = 0; i < 4; i++) {                                         \
            int off_ = (buf)*ASZ + (ar + i*32)*SBK + akc;                     \
            CVTSTORE(Ahi, Alo, off_, pa[i]);                                  \
        }                                                                     \
        _Pragma("unroll")                                                     \
        for (int i = 0; i < 2; i++) {                                         \
            int off_ = (buf)*BSZ + (ar + i*32)*SBK + akc;                     \
            CVTSTORE(Bhi, Blo, off_, pb[i]);                                  \
        }                                                                     \
    } while (0)

    LOADT(0);
    STORET(0);
    __syncthreads();

    int buf = 0;
    for (int k0 = 0; k0 < K; k0 += KT) {
        const bool more = (k0 + KT) < K;
        if (more) LOADT(k0 + KT);
        #pragma unroll
        for (int kk = 0; kk < KT; kk += 16) {
            wmma::fragment<wmma::matrix_b,16,16,16,__nv_bfloat16,wmma::col_major> bh[2], bl[2];
            #pragma unroll
            for (int j = 0; j < 2; j++) {
                wmma::load_matrix_sync(bh[j], &Bhi[buf*BSZ + (wn*32 + j*16)*SBK + kk], SBK);
                wmma::load_matrix_sync(bl[j], &Blo[buf*BSZ + (wn*32 + j*16)*SBK + kk], SBK);
            }
            #pragma unroll
            for (int i = 0; i < 2; i++) {
                wmma::fragment<wmma::matrix_a,16,16,16,__nv_bfloat16,wmma::row_major> ah, al;
                wmma::load_matrix_sync(ah, &Ahi[buf*ASZ + (wm*32 + i*16)*SBK + kk], SBK);
                wmma::load_matrix_sync(al, &Alo[buf*ASZ + (wm*32 + i*16)*SBK + kk], SBK);
                #pragma unroll
                for (int j = 0; j < 2; j++) {
                    wmma::mma_sync(acc[i][j], ah, bh[j], acc[i][j]);
                    wmma::mma_sync(acc[i][j], al, bh[j], acc[i][j]);
                    wmma::mma_sync(acc[i][j], ah, bl[j], acc[i][j]);
                }
            }
        }
        if (more) STORET(buf ^ 1);
        __syncthreads();
        buf ^= 1;
    }

    #pragma unroll
    for (int i = 0; i < 2; i++)
        #pragma unroll
        for (int j = 0; j < 2; j++)
            wmma::store_matrix_sync(
                &C[(size_t)(m0 + wm*32 + i*16)*Nout + n0 + wn*32 + j*16],
                acc[i][j], Nout, wmma::mem_row_major);
    #undef LOADT
    #undef STORET
}

// ---------------- LayerNorm over DIM=192 (patch bias folded in) -------------
__global__ void ln_kernel(float* __restrict__ tok, const float* __restrict__ pb,
                          const float* __restrict__ g, const float* __restrict__ b) {
    int row  = blockIdx.x * 8 + (threadIdx.x >> 5);
    int lane = threadIdx.x & 31;
    float* p = tok + (size_t)row * DIMV;
    float v[6]; float s = 0.f;
    #pragma unroll
    for (int i = 0; i < 6; i++) {
        int c = lane + i*32;
        v[i] = p[c] + pb[c];
        s += v[i];
    }
    #pragma unroll
    for (int o = 16; o; o >>= 1) s += __shfl_xor_sync(0xffffffffu, s, o);
    float mu = s * (1.0f/192.0f);
    float q = 0.f;
    #pragma unroll
    for (int i = 0; i < 6; i++) { float d = v[i] - mu; q = fmaf(d, d, q); }
    #pragma unroll
    for (int o = 16; o; o >>= 1) q += __shfl_xor_sync(0xffffffffu, q, o);
    float rstd = rsqrtf(q * (1.0f/192.0f) + 1e-5f);
    #pragma unroll
    for (int i = 0; i < 6; i++) {
        int c = lane + i*32;
        p[c] = (v[i] - mu) * rstd * g[c] + b[c];
    }
}

// ---------------- depthwise causal/anticausal conv + silu -------------------
__global__ void conv_silu_kernel(const float* __restrict__ cwf, const float* __restrict__ cbf,
                                 const float* __restrict__ cwb, const float* __restrict__ cbb) {
    int dir = blockIdx.y;
    int i = blockIdx.x * 256 + threadIdx.x;            // over MTOK*DIN
    if (i >= MTOK * DIN) return;
    int r = i / DIN, d = i - r * DIN;
    int b = r / SEQL, l = r - b * SEQL;
    const float* xz = g_xz[dir];
    const float* cw = dir ? cwb : cwf;
    const float* cb = dir ? cbb : cbf;
    float acc = cb[d];
    #pragma unroll
    for (int k = 0; k < 4; k++) {
        int ll = dir ? (l + 3 - k) : (l - 3 + k);
        if (ll >= 0 && ll < SEQL)
            acc = fmaf(xz[((size_t)(b*SEQL + ll))*(2*DIN) + d], cw[d*4 + k], acc);
    }
    g_xc[dir][i] = acc * __frcp_rn(1.0f + __expf(-acc));
}

// ---------------- dt = softplus(dt_raw @ dt_w^T + dt_b), K=12 ---------------
__global__ void dt_kernel(const float* __restrict__ wf, const float* __restrict__ bf,
                          const float* __restrict__ wb, const float* __restrict__ bb) {
    int dir = blockIdx.y;
    int r0 = blockIdx.x * 16;
    int d = threadIdx.x;                               // 384
    __shared__ float dtr[16][12];
    if (threadIdx.x < 192) {
        int rr = threadIdx.x / 12, k = threadIdx.x - rr*12;
        dtr[rr][k] = g_proj[dir][(size_t)(r0 + rr)*NPROJP + k];
    }
    const float* w = dir ? wb : wf;
    float wreg[12];
    #pragma unroll
    for (int k = 0; k < 12; k++) wreg[k] = w[d*12 + k];
    float bias = (dir ? bb : bf)[d];
    __syncthreads();
    #pragma unroll 4
    for (int rr = 0; rr < 16; rr++) {
        float acc = bias;
        #pragma unroll
        for (int k = 0; k < 12; k++) acc = fmaf(dtr[rr][k], wreg[k], acc);
        // softplus = max(x,0) + log1p(exp(-|x|))
        float sp = fmaxf(acc, 0.0f) + __logf(1.0f + __expf(-fabsf(acc)));
        g_dt[dir][(size_t)(r0 + rr)*DIN + d] = sp;
    }
}

// ---------------- selective scan; accumulates sum over L directly ----------
__global__ __launch_bounds__(128) void scan_kernel(
    const float* __restrict__ Alf, const float* __restrict__ Df,
    const float* __restrict__ Alb, const float* __restrict__ Db)
{
    int gid  = (blockIdx.x * 128 + threadIdx.x) >> 2;
    int lane = threadIdx.x & 3;
    if (gid >= 2 * BATCH * DIN) return;
    int dir = gid >= BATCH * DIN;
    int rem = gid - dir * BATCH * DIN;
    int b = rem / DIN, d = rem - b * DIN;
    const float* Alog = dir ? Alb : Alf;
    float Dv = (dir ? Db : Df)[d];
    float a0 = -__expf(Alog[d*DSTATE + lane*4 + 0]);
    float a1 = -__expf(Alog[d*DSTATE + lane*4 + 1]);
    float a2 = -__expf(Alog[d*DSTATE + lane*4 + 2]);
    float a3 = -__expf(Alog[d*DSTATE + lane*4 + 3]);
    const float* dtp = g_dt[dir];
    const float* xcp = g_xc[dir];
    const float* zp  = g_xz[dir];                      // z at [r*2*DIN + DIN + d]
    const float* pp  = g_proj[dir];
    float h0=0.f,h1=0.f,h2=0.f,h3=0.f, acc=0.f;
    int r    = b*SEQL + (dir ? SEQL - 1 : 0);
    int step = dir ? -1 : 1;

    size_t rd = (size_t)r * DIN + d;
    float dtv = dtp[rd], xcv = xcp[rd];
    float zv  = zp[(size_t)r*(2*DIN) + DIN + d];
    float4 Bv = *(const float4*)&pp[(size_t)r*NPROJP + DTRANK + lane*4];
    float4 Cv = *(const float4*)&pp[(size_t)r*NPROJP + DTRANK + DSTATE + lane*4];

    for (int t = 0; t < SEQL; t++) {
        int rn = r + step;
        float ndt = 0.f, nxc = 0.f, nz = 0.f;
        float4 nB = Bv, nC = Cv;
        if (t + 1 < SEQL) {
            size_t rdn = (size_t)rn * DIN + d;
            ndt = dtp[rdn]; nxc = xcp[rdn];
            nz  = zp[(size_t)rn*(2*DIN) + DIN + d];
            nB = *(const float4*)&pp[(size_t)rn*NPROJP + DTRANK + lane*4];
            nC = *(const float4*)&pp[(size_t)rn*NPROJP + DTRANK + DSTATE + lane*4];
        }
        float dtx = dtv * xcv;
        h0 = fmaf(__expf(dtv*a0), h0, dtx*Bv.x);
        h1 = fmaf(__expf(dtv*a1), h1, dtx*Bv.y);
        h2 = fmaf(__expf(dtv*a2), h2, dtx*Bv.z);
        h3 = fmaf(__expf(dtv*a3), h3, dtx*Bv.w);
        float part = fmaf(h0,Cv.x, fmaf(h1,Cv.y, fmaf(h2,Cv.z, h3*Cv.w)));
        part += __shfl_xor_sync(0xffffffffu, part, 1);
        part += __shfl_xor_sync(0xffffffffu, part, 2);
        float zs = zv * __frcp_rn(1.0f + __expf(-zv));
        acc = fmaf(fmaf(xcv, Dv, part), zs, acc);
        dtv = ndt; xcv = nxc; zv = nz; Bv = nB; Cv = nC; r = rn;
    }
    if (lane == 0) g_ysum[dir][b*DIN + d] = acc;
}

// ---------------- head: mean -> out_proj (both dirs) -> fc ------------------
__global__ void head_kernel(const float* __restrict__ fow, const float* __restrict__ bow,
                            const float* __restrict__ fcw, const float* __restrict__ fcb,
                            float* __restrict__ out) {
    int b = blockIdx.x;
    __shared__ float ys0[DIN], ys1[DIN], o[DIMV];
    int t = threadIdx.x;                               // 192
    for (int i = t; i < DIN; i += DIMV) {
        ys0[i] = g_ysum[0][b*DIN + i] * (1.0f/SEQL);
        ys1[i] = g_ysum[1][b*DIN + i] * (1.0f/SEQL);
    }
    __syncthreads();
    float acc = 0.f;
    #pragma unroll 4
    for (int di = 0; di < DIN; di++)
        acc = fmaf(ys0[di], fow[(size_t)t*DIN + di], fmaf(ys1[di], bow[(size_t)t*DIN + di], acc));
    o[t] = acc;
    __syncthreads();
    if (t < 4) {
        float s = fcb[t];
        #pragma unroll 4
        for (int d = 0; d < DIMV; d++) s = fmaf(o[d], fcw[t*DIMV + d], s);
        out[b*4 + t] = s;
    }
}

// ---------------- launch ----------------------------------------------------
extern "C" void kernel_launch(void* const* d_in, const int* in_sizes, int n_in,
                              void* d_out, int out_size) {
    (void)in_sizes; (void)n_in; (void)out_size;
    const float* x       = (const float*)d_in[0];
    const float* patch_w = (const float*)d_in[1];
    const float* patch_b = (const float*)d_in[2];
    const float* ln_g    = (const float*)d_in[3];
    const float* ln_b    = (const float*)d_in[4];
    const float* fc_w    = (const float*)d_in[5];
    const float* fc_b    = (const float*)d_in[6];
    // per-direction params: in_w, conv_w, conv_b, xproj_w, dt_w, dt_b, A_log, D, out_w
    const float* P[2][9];
    for (int dir = 0; dir < 2; dir++)
        for (int i = 0; i < 9; i++)
            P[dir][i] = (const float*)d_in[7 + dir*9 + i];

    float *tok, *xz, *xc, *proj;
    cudaGetSymbolAddress((void**)&tok,  g_tok);
    cudaGetSymbolAddress((void**)&xz,   g_xz);
    cudaGetSymbolAddress((void**)&xc,   g_xc);
    cudaGetSymbolAddress((void**)&proj, g_proj);

    cudaFuncSetAttribute(gemm_bfs_kernel<true>,
                         cudaFuncAttributeMaxDynamicSharedMemorySize, GEMM_SMEM);
    cudaFuncSetAttribute(gemm_bfs_kernel<false>,
                         cudaFuncAttributeMaxDynamicSharedMemorySize, GEMM_SMEM);

    // 1. patch embed GEMM with implicit im2col (bias folded into LN)
    gemm_bfs_kernel<true><<<dim3(DIMV/NT, MTOK/MT, 1), 256, GEMM_SMEM>>>(
        x, x, patch_w, patch_w, tok, tok, 768, DIMV, DIMV);
    // 2. layernorm in place (adds patch_b first)
    ln_kernel<<<MTOK/8, 256>>>(tok, patch_b, ln_g, ln_b);
    // 3. in-projection, both directions in one launch (grid.z)
    gemm_bfs_kernel<false><<<dim3((2*DIN)/NT, MTOK/MT, 2), 256, GEMM_SMEM>>>(
        tok, tok, P[0][0], P[1][0],
        xz, xz + (size_t)MTOK*2*DIN, DIMV, 2*DIN, 2*DIN);
    // 4. conv + silu
    conv_silu_kernel<<<dim3((MTOK*DIN)/256, 2), 256>>>(P[0][1], P[0][2], P[1][1], P[1][2]);
    // 5. x-projection (dt_raw | B | C), weights zero-padded 44 -> 64 cols
    gemm_bfs_kernel<false><<<dim3(1, MTOK/MT, 2), 256, GEMM_SMEM>>>(
        xc, xc + (size_t)MTOK*DIN, P[0][3], P[1][3],
        proj, proj + (size_t)MTOK*NPROJP, DIN, 44, NPROJP);
    // 6. dt projection + softplus
    dt_kernel<<<dim3(MTOK/16, 2), 384>>>(P[0][4], P[0][5], P[1][4], P[1][5]);
    // 7. selective scan (both directions), accumulating token-sum
    scan_kernel<<<(2*BATCH*DIN*4)/128, 128>>>(P[0][6], P[0][7], P[1][6], P[1][7]);
    // 8. head: mean-pool -> out_w (both dirs) -> fc
    head_kernel<<<BATCH, DIMV>>>(P[0][8], P[1][8], fc_w, fc_b, (float*)d_out);
}

// round 8
// speedup vs baseline: 1.6481x; 1.1240x over previous
#include <cuda_runtime.h>
#include <cuda_fp16.h>
#include <mma.h>
#include <cstdint>
#include <cstddef>

using namespace nvcuda;

// ---------------- problem constants ----------------
#define BATCH   32
#define SEQL    576                 // 24*24 tokens
#define MTOK    (BATCH*SEQL)        // 18432
#define DIMV    192
#define DIN     384                 // 2*DIM
#define DSTATE  16
#define DTRANK  12
#define NPROJP  64                  // padded proj row stride (real cols: 44)

// ---------------- scratch (device globals; no allocation) ----------------
__device__ float g_tok [(size_t)MTOK * DIMV];             // 14.2 MB
__device__ float g_xz  [2][(size_t)MTOK * 2*DIN];         // 113 MB (z-half becomes silu(z))
__device__ float g_xc  [2][(size_t)MTOK * DIN];           // 56.6 MB
__device__ float g_proj[2][(size_t)MTOK * NPROJP];        // 9.4 MB
__device__ float g_dt  [2][(size_t)MTOK * DIN];           // 56.6 MB
__device__ float g_ysum[2][BATCH * DIN];

// ---------------- fp16 WMMA GEMM -------------------------------------------
// C[M,Nout] = A[M,K] @ W[Nw,K]^T, rows of W beyond Nw are zero.
// fp16 operands (fp32 accumulate): per-dot relative error ~2^-12*sqrt(2),
// well under the 1e-3 gate. Block tile 128x64x32, 8 warps (4m x 2n),
// warp tile 32x32 = 2x2 wmma m16n16k16. Double-buffered smem.
// blockIdx.z selects (A,W,C) set 0 or 1 for fused dual-direction launches.
// IMC: implicit im2col of x[32,3,384,384] into A[MTOK, 768] (16x16 patches).
#define MT 128
#define NT 64
#define KT 32
#define SBK 40                      // smem row stride in halfs (pad 32->40)
#define ASZ (MT*SBK)                // 5120 halves per stage
#define BSZ (NT*SBK)                // 2560
#define GEMM_SMEM ((2*ASZ + 2*BSZ) * 2)   // bytes = 30720

#define CVTSTOREH(dst, off, v) do {                                           \
    __half2 h0_ = __floats2half2_rn((v).x, (v).y);                            \
    __half2 h1_ = __floats2half2_rn((v).z, (v).w);                            \
    *(__half2*)&(dst)[(off)]     = h0_;                                       \
    *(__half2*)&(dst)[(off) + 2] = h1_;                                       \
} while (0)

template<bool IMC>
__global__ __launch_bounds__(256, 2) void gemm_fp16_kernel(
    const float* __restrict__ A0, const float* __restrict__ A1,
    const float* __restrict__ W0, const float* __restrict__ W1,
    float* __restrict__ C0, float* __restrict__ C1,
    int K, int Nw, int Nout)
{
    extern __shared__ __half sm[];
    __half* As = sm;                    // [2][MT][SBK]
    __half* Bs = sm + 2*ASZ;            // [2][NT][SBK]

    const float* A = blockIdx.z ? A1 : A0;
    const float* W = blockIdx.z ? W1 : W0;
    float*       C = blockIdx.z ? C1 : C0;

    const int tid  = threadIdx.x;
    const int warp = tid >> 5;
    const int wm   = warp >> 1;      // 0..3 -> m offset wm*32
    const int wn   = warp & 1;       // 0..1 -> n offset wn*32
    const int m0 = blockIdx.y * MT;
    const int n0 = blockIdx.x * NT;
    const int ar = tid >> 3, akc = (tid & 7) * 4;

    int rb[4];
    if (IMC) {
        #pragma unroll
        for (int i = 0; i < 4; i++) {
            int tok = m0 + ar + i*32;
            int b = tok / SEQL, rl = tok - b*SEQL;
            int hp = rl / 24, wp = rl - hp*24;
            rb[i] = b*442368 + hp*6144 + wp*16;   // 3*384*384, 16*384
        }
    }

    wmma::fragment<wmma::accumulator,16,16,16,float> acc[2][2];
    #pragma unroll
    for (int i = 0; i < 2; i++)
        #pragma unroll
        for (int j = 0; j < 2; j++)
            wmma::fill_fragment(acc[i][j], 0.0f);

    float4 pa[4], pb[2];

    #define LOADT(k0)  do {                                                   \
        if (IMC) {                                                            \
            int k_ = (k0) + akc;                                              \
            int c_ = k_ >> 8, pq_ = k_ & 255;                                 \
            int koff_ = c_*147456 + (pq_ >> 4)*384 + (pq_ & 15);              \
            _Pragma("unroll")                                                 \
            for (int i = 0; i < 4; i++)                                       \
                pa[i] = *(const float4*)&A[rb[i] + koff_];                    \
        } else {                                                              \
            _Pragma("unroll")                                                 \
            for (int i = 0; i < 4; i++)                                       \
                pa[i] = *(const float4*)&A[(size_t)(m0 + ar + i*32)*K + (k0) + akc]; \
        }                                                                     \
        _Pragma("unroll")                                                     \
        for (int i = 0; i < 2; i++) {                                         \
            int r_ = ar + i*32;                                               \
            pb[i] = (n0 + r_ < Nw)                                            \
                ? *(const float4*)&W[(size_t)(n0 + r_)*K + (k0) + akc]        \
                : make_float4(0.f,0.f,0.f,0.f);                               \
        }                                                                     \
    } while (0)

    #define STORET(buf)  do {                                                 \
        _Pragma("unroll")                                                     \
        for (int i = 0; i < 4; i++)                                           \
            CVTSTOREH(As, (buf)*ASZ + (ar + i*32)*SBK + akc, pa[i]);          \
        _Pragma("unroll")                                                     \
        for (int i = 0; i < 2; i++)                                           \
            CVTSTOREH(Bs, (buf)*BSZ + (ar + i*32)*SBK + akc, pb[i]);          \
    } while (0)

    LOADT(0);
    STORET(0);
    __syncthreads();

    int buf = 0;
    for (int k0 = 0; k0 < K; k0 += KT) {
        const bool more = (k0 + KT) < K;
        if (more) LOADT(k0 + KT);
        #pragma unroll
        for (int kk = 0; kk < KT; kk += 16) {
            wmma::fragment<wmma::matrix_b,16,16,16,__half,wmma::col_major> bf[2];
            #pragma unroll
            for (int j = 0; j < 2; j++)
                wmma::load_matrix_sync(bf[j], &Bs[buf*BSZ + (wn*32 + j*16)*SBK + kk], SBK);
            #pragma unroll
            for (int i = 0; i < 2; i++) {
                wmma::fragment<wmma::matrix_a,16,16,16,__half,wmma::row_major> af;
                wmma::load_matrix_sync(af, &As[buf*ASZ + (wm*32 + i*16)*SBK + kk], SBK);
                #pragma unroll
                for (int j = 0; j < 2; j++)
                    wmma::mma_sync(acc[i][j], af, bf[j], acc[i][j]);
            }
        }
        if (more) STORET(buf ^ 1);
        __syncthreads();
        buf ^= 1;
    }

    #pragma unroll
    for (int i = 0; i < 2; i++)
        #pragma unroll
        for (int j = 0; j < 2; j++)
            wmma::store_matrix_sync(
                &C[(size_t)(m0 + wm*32 + i*16)*Nout + n0 + wn*32 + j*16],
                acc[i][j], Nout, wmma::mem_row_major);
    #undef LOADT
    #undef STORET
}

// ---------------- LayerNorm over DIM=192 (patch bias folded in) -------------
__global__ void ln_kernel(float* __restrict__ tok, const float* __restrict__ pb,
                          const float* __restrict__ g, const float* __restrict__ b) {
    int row  = blockIdx.x * 8 + (threadIdx.x >> 5);
    int lane = threadIdx.x & 31;
    float* p = tok + (size_t)row * DIMV;
    float v[6]; float s = 0.f;
    #pragma unroll
    for (int i = 0; i < 6; i++) {
        int c = lane + i*32;
        v[i] = p[c] + pb[c];
        s += v[i];
    }
    #pragma unroll
    for (int o = 16; o; o >>= 1) s += __shfl_xor_sync(0xffffffffu, s, o);
    float mu = s * (1.0f/192.0f);
    float q = 0.f;
    #pragma unroll
    for (int i = 0; i < 6; i++) { float d = v[i] - mu; q = fmaf(d, d, q); }
    #pragma unroll
    for (int o = 16; o; o >>= 1) q += __shfl_xor_sync(0xffffffffu, q, o);
    float rstd = rsqrtf(q * (1.0f/192.0f) + 1e-5f);
    #pragma unroll
    for (int i = 0; i < 6; i++) {
        int c = lane + i*32;
        p[c] = (v[i] - mu) * rstd * g[c] + b[c];
    }
}

// ---------------- conv + silu (sliding window) + silu(z) in place ----------
// One thread per float4-of-d; 32-token l-chunks with 3-token halo.
// Both directions use the same tap formula: xc[l] = sum_k cw[k]*w[k] with
// w[k] = x[l - (3-k)*s], s=+1 fwd / s=-1 bwd  (w3 = newest = x[l]).
// Also rewrites the z-half of g_xz with silu(z) so the scan reads it directly.
__device__ __forceinline__ float4 silu4(float4 v) {
    float4 r;
    r.x = v.x * __frcp_rn(1.0f + __expf(-v.x));
    r.y = v.y * __frcp_rn(1.0f + __expf(-v.y));
    r.z = v.z * __frcp_rn(1.0f + __expf(-v.z));
    r.w = v.w * __frcp_rn(1.0f + __expf(-v.w));
    return r;
}

__global__ __launch_bounds__(96) void conv_silu_kernel(
    const float* __restrict__ cwf, const float* __restrict__ cbf,
    const float* __restrict__ cwb, const float* __restrict__ cbb)
{
    const int dir = blockIdx.z;
    const int b   = blockIdx.y;
    const int l0  = blockIdx.x * 32;
    const int d   = threadIdx.x * 4;          // 0..380
    const float* cw = dir ? cwb : cwf;
    const float* cb = dir ? cbb : cbf;

    // transpose conv weights into per-tap float4s
    float4 a0 = *(const float4*)&cw[(d+0)*4];
    float4 a1 = *(const float4*)&cw[(d+1)*4];
    float4 a2 = *(const float4*)&cw[(d+2)*4];
    float4 a3 = *(const float4*)&cw[(d+3)*4];
    float4 t0 = make_float4(a0.x, a1.x, a2.x, a3.x);
    float4 t1 = make_float4(a0.y, a1.y, a2.y, a3.y);
    float4 t2 = make_float4(a0.z, a1.z, a2.z, a3.z);
    float4 t3 = make_float4(a0.w, a1.w, a2.w, a3.w);
    float4 bias = *(const float4*)&cb[d];

    float* xz = g_xz[dir];
    float* xc = g_xc[dir];
    const int s  = dir ? -1 : 1;
    int l = dir ? (l0 + 31) : l0;

    #define LDX(ll) ((unsigned)(ll) < SEQL                                     \
        ? *(const float4*)&xz[((size_t)(b*SEQL + (ll)))*(2*DIN) + d]           \
        : make_float4(0.f,0.f,0.f,0.f))

    float4 w0 = LDX(l - 3*s);
    float4 w1 = LDX(l - 2*s);
    float4 w2 = LDX(l - 1*s);

    #pragma unroll 4
    for (int i = 0; i < 32; i++, l += s) {
        size_t row = (size_t)(b*SEQL + l) * (2*DIN);
        float4 w3 = *(const float4*)&xz[row + d];
        float4 r;
        r.x = fmaf(t3.x, w3.x, fmaf(t2.x, w2.x, fmaf(t1.x, w1.x, fmaf(t0.x, w0.x, bias.x))));
        r.y = fmaf(t3.y, w3.y, fmaf(t2.y, w2.y, fmaf(t1.y, w1.y, fmaf(t0.y, w0.y, bias.y))));
        r.z = fmaf(t3.z, w3.z, fmaf(t2.z, w2.z, fmaf(t1.z, w1.z, fmaf(t0.z, w0.z, bias.z))));
        r.w = fmaf(t3.w, w3.w, fmaf(t2.w, w2.w, fmaf(t1.w, w1.w, fmaf(t0.w, w0.w, bias.w))));
        *(float4*)&xc[(size_t)(b*SEQL + l)*DIN + d] = silu4(r);
        float4 zv = *(const float4*)&xz[row + DIN + d];
        *(float4*)&xz[row + DIN + d] = silu4(zv);
        w0 = w1; w1 = w2; w2 = w3;
    }
    #undef LDX
}

// ---------------- dt = softplus(dt_raw @ dt_w^T + dt_b), K=12 ---------------
__global__ void dt_kernel(const float* __restrict__ wf, const float* __restrict__ bf,
                          const float* __restrict__ wb, const float* __restrict__ bb) {
    int dir = blockIdx.y;
    int r0 = blockIdx.x * 16;
    int d = threadIdx.x;                               // 384
    __shared__ float dtr[16][12];
    if (threadIdx.x < 192) {
        int rr = threadIdx.x / 12, k = threadIdx.x - rr*12;
        dtr[rr][k] = g_proj[dir][(size_t)(r0 + rr)*NPROJP + k];
    }
    const float* w = dir ? wb : wf;
    float wreg[12];
    #pragma unroll
    for (int k = 0; k < 12; k++) wreg[k] = w[d*12 + k];
    float bias = (dir ? bb : bf)[d];
    __syncthreads();
    #pragma unroll 4
    for (int rr = 0; rr < 16; rr++) {
        float acc = bias;
        #pragma unroll
        for (int k = 0; k < 12; k++) acc = fmaf(dtr[rr][k], wreg[k], acc);
        float sp = fmaxf(acc, 0.0f) + __logf(1.0f + __expf(-fabsf(acc)));
        g_dt[dir][(size_t)(r0 + rr)*DIN + d] = sp;
    }
}

// ---------------- selective scan; accumulates sum over L directly ----------
// silu(z) precomputed (z-half of g_xz).
__global__ __launch_bounds__(128) void scan_kernel(
    const float* __restrict__ Alf, const float* __restrict__ Df,
    const float* __restrict__ Alb, const float* __restrict__ Db)
{
    int gid  = (blockIdx.x * 128 + threadIdx.x) >> 2;
    int lane = threadIdx.x & 3;
    if (gid >= 2 * BATCH * DIN) return;
    int dir = gid >= BATCH * DIN;
    int rem = gid - dir * BATCH * DIN;
    int b = rem / DIN, d = rem - b * DIN;
    const float* Alog = dir ? Alb : Alf;
    float Dv = (dir ? Db : Df)[d];
    float a0 = -__expf(Alog[d*DSTATE + lane*4 + 0]);
    float a1 = -__expf(Alog[d*DSTATE + lane*4 + 1]);
    float a2 = -__expf(Alog[d*DSTATE + lane*4 + 2]);
    float a3 = -__expf(Alog[d*DSTATE + lane*4 + 3]);
    const float* dtp = g_dt[dir];
    const float* xcp = g_xc[dir];
    const float* zp  = g_xz[dir];                      // silu(z) at [r*2*DIN + DIN + d]
    const float* pp  = g_proj[dir];
    float h0=0.f,h1=0.f,h2=0.f,h3=0.f, acc=0.f;
    int r    = b*SEQL + (dir ? SEQL - 1 : 0);
    int step = dir ? -1 : 1;

    size_t rd = (size_t)r * DIN + d;
    float dtv = dtp[rd], xcv = xcp[rd];
    float zs  = zp[(size_t)r*(2*DIN) + DIN + d];
    float4 Bv = *(const float4*)&pp[(size_t)r*NPROJP + DTRANK + lane*4];
    float4 Cv = *(const float4*)&pp[(size_t)r*NPROJP + DTRANK + DSTATE + lane*4];

    for (int t = 0; t < SEQL; t++) {
        int rn = r + step;
        float ndt = 0.f, nxc = 0.f, nz = 0.f;
        float4 nB = Bv, nC = Cv;
        if (t + 1 < SEQL) {
            size_t rdn = (size_t)rn * DIN + d;
            ndt = dtp[rdn]; nxc = xcp[rdn];
            nz  = zp[(size_t)rn*(2*DIN) + DIN + d];
            nB = *(const float4*)&pp[(size_t)rn*NPROJP + DTRANK + lane*4];
            nC = *(const float4*)&pp[(size_t)rn*NPROJP + DTRANK + DSTATE + lane*4];
        }
        float dtx = dtv * xcv;
        h0 = fmaf(__expf(dtv*a0), h0, dtx*Bv.x);
        h1 = fmaf(__expf(dtv*a1), h1, dtx*Bv.y);
        h2 = fmaf(__expf(dtv*a2), h2, dtx*Bv.z);
        h3 = fmaf(__expf(dtv*a3), h3, dtx*Bv.w);
        float part = fmaf(h0,Cv.x, fmaf(h1,Cv.y, fmaf(h2,Cv.z, h3*Cv.w)));
        part += __shfl_xor_sync(0xffffffffu, part, 1);
        part += __shfl_xor_sync(0xffffffffu, part, 2);
        acc = fmaf(fmaf(xcv, Dv, part), zs, acc);
        dtv = ndt; xcv = nxc; zs = nz; Bv = nB; Cv = nC; r = rn;
    }
    if (lane == 0) g_ysum[dir][b*DIN + d] = acc;
}

// ---------------- head: mean -> out_proj (both dirs) -> fc ------------------
__global__ void head_kernel(const float* __restrict__ fow, const float* __restrict__ bow,
                            const float* __restrict__ fcw, const float* __restrict__ fcb,
                            float* __restrict__ out) {
    int b = blockIdx.x;
    __shared__ float ys0[DIN], ys1[DIN], o[DIMV];
    int t = threadIdx.x;                               // 192
    for (int i = t; i < DIN; i += DIMV) {
        ys0[i] = g_ysum[0][b*DIN + i] * (1.0f/SEQL);
        ys1[i] = g_ysum[1][b*DIN + i] * (1.0f/SEQL);
    }
    __syncthreads();
    float acc = 0.f;
    #pragma unroll 4
    for (int di = 0; di < DIN; di++)
        acc = fmaf(ys0[di], fow[(size_t)t*DIN + di], fmaf(ys1[di], bow[(size_t)t*DIN + di], acc));
    o[t] = acc;
    __syncthreads();
    if (t < 4) {
        float s = fcb[t];
        #pragma unroll 4
        for (int d = 0; d < DIMV; d++) s = fmaf(o[d], fcw[t*DIMV + d], s);
        out[b*4 + t] = s;
    }
}

// ---------------- launch ----------------------------------------------------
extern "C" void kernel_launch(void* const* d_in, const int* in_sizes, int n_in,
                              void* d_out, int out_size) {
    (void)in_sizes; (void)n_in; (void)out_size;
    const float* x       = (const float*)d_in[0];
    const float* patch_w = (const float*)d_in[1];
    const float* patch_b = (const float*)d_in[2];
    const float* ln_g    = (const float*)d_in[3];
    const float* ln_b    = (const float*)d_in[4];
    const float* fc_w    = (const float*)d_in[5];
    const float* fc_b    = (const float*)d_in[6];
    // per-direction params: in_w, conv_w, conv_b, xproj_w, dt_w, dt_b, A_log, D, out_w
    const float* P[2][9];
    for (int dir = 0; dir < 2; dir++)
        for (int i = 0; i < 9; i++)
            P[dir][i] = (const float*)d_in[7 + dir*9 + i];

    float *tok, *xz, *xc, *proj;
    cudaGetSymbolAddress((void**)&tok,  g_tok);
    cudaGetSymbolAddress((void**)&xz,   g_xz);
    cudaGetSymbolAddress((void**)&xc,   g_xc);
    cudaGetSymbolAddress((void**)&proj, g_proj);

    cudaFuncSetAttribute(gemm_fp16_kernel<true>,
                         cudaFuncAttributeMaxDynamicSharedMemorySize, GEMM_SMEM);
    cudaFuncSetAttribute(gemm_fp16_kernel<false>,
                         cudaFuncAttributeMaxDynamicSharedMemorySize, GEMM_SMEM);

    // 1. patch embed GEMM with implicit im2col (bias folded into LN)
    gemm_fp16_kernel<true><<<dim3(DIMV/NT, MTOK/MT, 1), 256, GEMM_SMEM>>>(
        x, x, patch_w, patch_w, tok, tok, 768, DIMV, DIMV);
    // 2. layernorm in place (adds patch_b first)
    ln_kernel<<<MTOK/8, 256>>>(tok, patch_b, ln_g, ln_b);
    // 3. in-projection, both directions in one launch (grid.z)
    gemm_fp16_kernel<false><<<dim3((2*DIN)/NT, MTOK/MT, 2), 256, GEMM_SMEM>>>(
        tok, tok, P[0][0], P[1][0],
        xz, xz + (size_t)MTOK*2*DIN, DIMV, 2*DIN, 2*DIN);
    // 4. conv + silu (+ silu(z) in place)
    conv_silu_kernel<<<dim3(SEQL/32, BATCH, 2), 96>>>(P[0][1], P[0][2], P[1][1], P[1][2]);
    // 5. x-projection (dt_raw | B | C), weights zero-padded 44 -> 64 cols
    gemm_fp16_kernel<false><<<dim3(1, MTOK/MT, 2), 256, GEMM_SMEM>>>(
        xc, xc + (size_t)MTOK*DIN, P[0][3], P[1][3],
        proj, proj + (size_t)MTOK*NPROJP, DIN, 44, NPROJP);
    // 6. dt projection + softplus
    dt_kernel<<<dim3(MTOK/16, 2), 384>>>(P[0][4], P[0][5], P[1][4], P[1][5]);
    // 7. selective scan (both directions), accumulating token-sum
    scan_kernel<<<(2*BATCH*DIN*4)/128, 128>>>(P[0][6], P[0][7], P[1][6], P[1][7]);
    // 8. head: mean-pool -> out_w (both dirs) -> fc
    head_kernel<<<BATCH, DIMV>>>(P[0][8], P[1][8], fc_w, fc_b, (float*)d_out);
}

// round 9
// speedup vs baseline: 1.8102x; 1.0984x over previous
#include <cuda_runtime.h>
#include <cuda_fp16.h>
#include <mma.h>
#include <cstdint>
#include <cstddef>

using namespace nvcuda;

// ---------------- problem constants ----------------
#define BATCH   32
#define SEQL    576                 // 24*24 tokens
#define MTOK    (BATCH*SEQL)        // 18432
#define DIMV    192
#define DIN     384                 // 2*DIM
#define DSTATE  16
#define DTRANK  12
#define NPROJP  64                  // padded proj row stride (real cols: 44)

// ---------------- scratch (device globals; no allocation) ----------------
__device__ float g_tok [(size_t)MTOK * DIMV];             // 14.2 MB
__device__ float g_xi  [2][(size_t)MTOK * DIN];           // 56.6 MB  raw x (pre-conv)
__device__ float g_zs  [2][(size_t)MTOK * DIN];           // 56.6 MB  silu(z) (from GEMM epi)
__device__ float g_xc  [2][(size_t)MTOK * DIN];           // 56.6 MB  silu(conv(x))
__device__ float g_proj[2][(size_t)MTOK * NPROJP];        // 9.4 MB   [dt_raw|B|C|pad]
__device__ float g_ysum[2][BATCH * DIN];

// ---------------- fp16 WMMA GEMM -------------------------------------------
// C[M,Nout] = A[M,K] @ W[Nw,K]^T, rows of W beyond Nw are zero.
// fp16 operands, fp32 accumulate. Block tile 128x64x32, 8 warps (4m x 2n),
// warp tile 32x32 = 2x2 wmma m16n16k16. Double-buffered smem.
// blockIdx.z selects (A,W,C) set 0/1 for fused dual-direction launches.
// IMC: implicit im2col of x[32,3,384,384] into A[MTOK,768] (16x16 patches).
// ZSPLIT: output cols [0,DIN) -> Cx raw; cols [DIN,2*DIN) -> Cz with silu
//         applied to the accumulator fragment. Both row-stride Nout(=DIN).
#define MT 128
#define NT 64
#define KT 32
#define SBK 40                      // smem row stride in halfs (pad 32->40)
#define ASZ (MT*SBK)
#define BSZ (NT*SBK)
#define GEMM_SMEM ((2*ASZ + 2*BSZ) * 2)   // 30720 bytes

#define CVTSTOREH(dst, off, v) do {                                           \
    __half2 h0_ = __floats2half2_rn((v).x, (v).y);                            \
    __half2 h1_ = __floats2half2_rn((v).z, (v).w);                            \
    *(__half2*)&(dst)[(off)]     = h0_;                                       \
    *(__half2*)&(dst)[(off) + 2] = h1_;                                       \
} while (0)

template<bool IMC, bool ZSPLIT>
__global__ __launch_bounds__(256) void gemm_fp16_kernel(
    const float* __restrict__ A0, const float* __restrict__ A1,
    const float* __restrict__ W0, const float* __restrict__ W1,
    float* __restrict__ Cx0, float* __restrict__ Cx1,
    float* __restrict__ Cz0, float* __restrict__ Cz1,
    int K, int Nw, int Nout)
{
    extern __shared__ __half sm[];
    __half* As = sm;                    // [2][MT][SBK]
    __half* Bs = sm + 2*ASZ;            // [2][NT][SBK]

    const float* A  = blockIdx.z ? A1 : A0;
    const float* W  = blockIdx.z ? W1 : W0;
    float*       Cx = blockIdx.z ? Cx1 : Cx0;
    float*       Cz = blockIdx.z ? Cz1 : Cz0;

    const int tid  = threadIdx.x;
    const int warp = tid >> 5;
    const int wm   = warp >> 1;      // 0..3 -> m offset wm*32
    const int wn   = warp & 1;       // 0..1 -> n offset wn*32
    const int m0 = blockIdx.y * MT;
    const int n0 = blockIdx.x * NT;
    const int ar = tid >> 3, akc = (tid & 7) * 4;

    int rb[4];
    if (IMC) {
        #pragma unroll
        for (int i = 0; i < 4; i++) {
            int tok = m0 + ar + i*32;
            int b = tok / SEQL, rl = tok - b*SEQL;
            int hp = rl / 24, wp = rl - hp*24;
            rb[i] = b*442368 + hp*6144 + wp*16;   // 3*384*384, 16*384
        }
    }

    wmma::fragment<wmma::accumulator,16,16,16,float> acc[2][2];
    #pragma unroll
    for (int i = 0; i < 2; i++)
        #pragma unroll
        for (int j = 0; j < 2; j++)
            wmma::fill_fragment(acc[i][j], 0.0f);

    float4 pa[4], pb[2];

    #define LOADT(k0)  do {                                                   \
        if (IMC) {                                                            \
            int k_ = (k0) + akc;                                              \
            int c_ = k_ >> 8, pq_ = k_ & 255;                                 \
            int koff_ = c_*147456 + (pq_ >> 4)*384 + (pq_ & 15);              \
            _Pragma("unroll")                                                 \
            for (int i = 0; i < 4; i++)                                       \
                pa[i] = *(const float4*)&A[rb[i] + koff_];                    \
        } else {                                                              \
            _Pragma("unroll")                                                 \
            for (int i = 0; i < 4; i++)                                       \
                pa[i] = *(const float4*)&A[(size_t)(m0 + ar + i*32)*K + (k0) + akc]; \
        }                                                                     \
        _Pragma("unroll")                                                     \
        for (int i = 0; i < 2; i++) {                                         \
            int r_ = ar + i*32;                                               \
            pb[i] = (n0 + r_ < Nw)                                            \
                ? *(const float4*)&W[(size_t)(n0 + r_)*K + (k0) + akc]        \
                : make_float4(0.f,0.f,0.f,0.f);                               \
        }                                                                     \
    } while (0)

    #define STORET(buf)  do {                                                 \
        _Pragma("unroll")                                                     \
        for (int i = 0; i < 4; i++)                                           \
            CVTSTOREH(As, (buf)*ASZ + (ar + i*32)*SBK + akc, pa[i]);          \
        _Pragma("unroll")                                                     \
        for (int i = 0; i < 2; i++)                                           \
            CVTSTOREH(Bs, (buf)*BSZ + (ar + i*32)*SBK + akc, pb[i]);          \
    } while (0)

    LOADT(0);
    STORET(0);
    __syncthreads();

    int buf = 0;
    for (int k0 = 0; k0 < K; k0 += KT) {
        const bool more = (k0 + KT) < K;
        if (more) LOADT(k0 + KT);
        #pragma unroll
        for (int kk = 0; kk < KT; kk += 16) {
            wmma::fragment<wmma::matrix_b,16,16,16,__half,wmma::col_major> bf[2];
            #pragma unroll
            for (int j = 0; j < 2; j++)
                wmma::load_matrix_sync(bf[j], &Bs[buf*BSZ + (wn*32 + j*16)*SBK + kk], SBK);
            #pragma unroll
            for (int i = 0; i < 2; i++) {
                wmma::fragment<wmma::matrix_a,16,16,16,__half,wmma::row_major> af;
                wmma::load_matrix_sync(af, &As[buf*ASZ + (wm*32 + i*16)*SBK + kk], SBK);
                #pragma unroll
                for (int j = 0; j < 2; j++)
                    wmma::mma_sync(acc[i][j], af, bf[j], acc[i][j]);
            }
        }
        if (more) STORET(buf ^ 1);
        __syncthreads();
        buf ^= 1;
    }

    #pragma unroll
    for (int i = 0; i < 2; i++)
        #pragma unroll
        for (int j = 0; j < 2; j++) {
            int nc = n0 + wn*32 + j*16;
            float* dst;
            if (ZSPLIT && nc >= DIN) {
                // z-half: apply silu in registers, store to Cz
                #pragma unroll
                for (int t = 0; t < acc[i][j].num_elements; t++) {
                    float v = acc[i][j].x[t];
                    acc[i][j].x[t] = v * __frcp_rn(1.0f + __expf(-v));
                }
                dst = &Cz[(size_t)(m0 + wm*32 + i*16)*Nout + nc - DIN];
            } else {
                dst = &Cx[(size_t)(m0 + wm*32 + i*16)*Nout + nc];
            }
            wmma::store_matrix_sync(dst, acc[i][j], Nout, wmma::mem_row_major);
        }
    #undef LOADT
    #undef STORET
}

// ---------------- LayerNorm over DIM=192 (patch bias folded in) -------------
__global__ void ln_kernel(float* __restrict__ tok, const float* __restrict__ pb,
                          const float* __restrict__ g, const float* __restrict__ b) {
    int row  = blockIdx.x * 8 + (threadIdx.x >> 5);
    int lane = threadIdx.x & 31;
    float* p = tok + (size_t)row * DIMV;
    float v[6]; float s = 0.f;
    #pragma unroll
    for (int i = 0; i < 6; i++) {
        int c = lane + i*32;
        v[i] = p[c] + pb[c];
        s += v[i];
    }
    #pragma unroll
    for (int o = 16; o; o >>= 1) s += __shfl_xor_sync(0xffffffffu, s, o);
    float mu = s * (1.0f/192.0f);
    float q = 0.f;
    #pragma unroll
    for (int i = 0; i < 6; i++) { float d = v[i] - mu; q = fmaf(d, d, q); }
    #pragma unroll
    for (int o = 16; o; o >>= 1) q += __shfl_xor_sync(0xffffffffu, q, o);
    float rstd = rsqrtf(q * (1.0f/192.0f) + 1e-5f);
    #pragma unroll
    for (int i = 0; i < 6; i++) {
        int c = lane + i*32;
        p[c] = (v[i] - mu) * rstd * g[c] + b[c];
    }
}

// ---------------- conv + silu (sliding window over dense x rows) ------------
// xc[l] = silu(bias + sum_k cw[k]*x[l - (3-k)*s]),  s=+1 fwd / -1 bwd.
// One thread per float4-of-d; 16-token l-chunks with 3-token halo.
__device__ __forceinline__ float4 silu4(float4 v) {
    float4 r;
    r.x = v.x * __frcp_rn(1.0f + __expf(-v.x));
    r.y = v.y * __frcp_rn(1.0f + __expf(-v.y));
    r.z = v.z * __frcp_rn(1.0f + __expf(-v.z));
    r.w = v.w * __frcp_rn(1.0f + __expf(-v.w));
    return r;
}

__global__ __launch_bounds__(96) void conv_silu_kernel(
    const float* __restrict__ cwf, const float* __restrict__ cbf,
    const float* __restrict__ cwb, const float* __restrict__ cbb)
{
    const int dir = blockIdx.z;
    const int b   = blockIdx.y;
    const int l0  = blockIdx.x * 16;
    const int d   = threadIdx.x * 4;          // 0..380
    const float* cw = dir ? cwb : cwf;
    const float* cb = dir ? cbb : cbf;

    float4 a0 = *(const float4*)&cw[(d+0)*4];
    float4 a1 = *(const float4*)&cw[(d+1)*4];
    float4 a2 = *(const float4*)&cw[(d+2)*4];
    float4 a3 = *(const float4*)&cw[(d+3)*4];
    float4 t0 = make_float4(a0.x, a1.x, a2.x, a3.x);
    float4 t1 = make_float4(a0.y, a1.y, a2.y, a3.y);
    float4 t2 = make_float4(a0.z, a1.z, a2.z, a3.z);
    float4 t3 = make_float4(a0.w, a1.w, a2.w, a3.w);
    float4 bias = *(const float4*)&cb[d];

    const float* xi = g_xi[dir];
    float* xc = g_xc[dir];
    const int s  = dir ? -1 : 1;
    int l = dir ? (l0 + 15) : l0;

    #define LDX(ll) ((unsigned)(ll) < SEQL                                     \
        ? *(const float4*)&xi[((size_t)(b*SEQL + (ll)))*DIN + d]               \
        : make_float4(0.f,0.f,0.f,0.f))

    float4 w0 = LDX(l - 3*s);
    float4 w1 = LDX(l - 2*s);
    float4 w2 = LDX(l - 1*s);

    #pragma unroll 4
    for (int i = 0; i < 16; i++, l += s) {
        float4 w3 = *(const float4*)&xi[(size_t)(b*SEQL + l)*DIN + d];
        float4 r;
        r.x = fmaf(t3.x, w3.x, fmaf(t2.x, w2.x, fmaf(t1.x, w1.x, fmaf(t0.x, w0.x, bias.x))));
        r.y = fmaf(t3.y, w3.y, fmaf(t2.y, w2.y, fmaf(t1.y, w1.y, fmaf(t0.y, w0.y, bias.y))));
        r.z = fmaf(t3.z, w3.z, fmaf(t2.z, w2.z, fmaf(t1.z, w1.z, fmaf(t0.z, w0.z, bias.z))));
        r.w = fmaf(t3.w, w3.w, fmaf(t2.w, w2.w, fmaf(t1.w, w1.w, fmaf(t0.w, w0.w, bias.w))));
        *(float4*)&xc[(size_t)(b*SEQL + l)*DIN + d] = silu4(r);
        w0 = w1; w1 = w2; w2 = w3;
    }
    #undef LDX
}

// ---------------- selective scan (dt fused); accumulates sum over L --------
// one 4-lane group per (dir,b,d); 4 states per lane; software-pipelined.
// dt = softplus(dot(proj[r,0:12], dt_w[d]) + dt_b[d]) computed inline:
// lane ln loads proj float4 at col ln*4 (lanes 0-2 hold dt_raw; lane 3's
// weights are zero), partial dot, 2x shfl reduce within the group.
__global__ __launch_bounds__(128) void scan_kernel(
    const float* __restrict__ Alf, const float* __restrict__ Df,
    const float* __restrict__ Alb, const float* __restrict__ Db,
    const float* __restrict__ dtwf, const float* __restrict__ dtbf,
    const float* __restrict__ dtwb, const float* __restrict__ dtbb)
{
    int gid  = (blockIdx.x * 128 + threadIdx.x) >> 2;
    int lane = threadIdx.x & 3;
    if (gid >= 2 * BATCH * DIN) return;
    int dir = gid >= BATCH * DIN;
    int rem = gid - dir * BATCH * DIN;
    int b = rem / DIN, d = rem - b * DIN;
    const float* Alog = dir ? Alb : Alf;
    float Dv = (dir ? Db : Df)[d];
    float a0 = -__expf(Alog[d*DSTATE + lane*4 + 0]);
    float a1 = -__expf(Alog[d*DSTATE + lane*4 + 1]);
    float a2 = -__expf(Alog[d*DSTATE + lane*4 + 2]);
    float a3 = -__expf(Alog[d*DSTATE + lane*4 + 3]);
    // dt weights for this lane (zero for lane 3)
    const float* dtw = dir ? dtwb : dtwf;
    float dtbias = (dir ? dtbb : dtbf)[d];
    float w0dt = 0.f, w1dt = 0.f, w2dt = 0.f, w3dt = 0.f;
    if (lane < 3) {
        w0dt = dtw[d*DTRANK + lane*4 + 0];
        w1dt = dtw[d*DTRANK + lane*4 + 1];
        w2dt = dtw[d*DTRANK + lane*4 + 2];
        w3dt = dtw[d*DTRANK + lane*4 + 3];
    }
    const float* xcp = g_xc[dir];
    const float* zp  = g_zs[dir];
    const float* pp  = g_proj[dir];
    float h0=0.f,h1=0.f,h2=0.f,h3=0.f, acc=0.f;
    int r    = b*SEQL + (dir ? SEQL - 1 : 0);
    int step = dir ? -1 : 1;

    float  xcv = xcp[(size_t)r*DIN + d];
    float  zs  = zp[(size_t)r*DIN + d];
    float4 Tv = *(const float4*)&pp[(size_t)r*NPROJP + lane*4];                    // dt_raw
    float4 Bv = *(const float4*)&pp[(size_t)r*NPROJP + DTRANK + lane*4];
    float4 Cv = *(const float4*)&pp[(size_t)r*NPROJP + DTRANK + DSTATE + lane*4];

    for (int t = 0; t < SEQL; t++) {
        int rn = r + step;
        float nxc = 0.f, nz = 0.f;
        float4 nT = Tv, nB = Bv, nC = Cv;
        if (t + 1 < SEQL) {
            size_t rdn = (size_t)rn * DIN + d;
            nxc = xcp[rdn];
            nz  = zp[rdn];
            nT = *(const float4*)&pp[(size_t)rn*NPROJP + lane*4];
            nB = *(const float4*)&pp[(size_t)rn*NPROJP + DTRANK + lane*4];
            nC = *(const float4*)&pp[(size_t)rn*NPROJP + DTRANK + DSTATE + lane*4];
        }
        // dt projection + softplus
        float dp = fmaf(w3dt, Tv.w, fmaf(w2dt, Tv.z, fmaf(w1dt, Tv.y, w0dt*Tv.x)));
        dp += __shfl_xor_sync(0xffffffffu, dp, 1);
        dp += __shfl_xor_sync(0xffffffffu, dp, 2);
        dp += dtbias;
        float dtv = fmaxf(dp, 0.0f) + __logf(1.0f + __expf(-fabsf(dp)));
        // state update
        float dtx = dtv * xcv;
        h0 = fmaf(__expf(dtv*a0), h0, dtx*Bv.x);
        h1 = fmaf(__expf(dtv*a1), h1, dtx*Bv.y);
        h2 = fmaf(__expf(dtv*a2), h2, dtx*Bv.z);
        h3 = fmaf(__expf(dtv*a3), h3, dtx*Bv.w);
        float part = fmaf(h0,Cv.x, fmaf(h1,Cv.y, fmaf(h2,Cv.z, h3*Cv.w)));
        part += __shfl_xor_sync(0xffffffffu, part, 1);
        part += __shfl_xor_sync(0xffffffffu, part, 2);
        acc = fmaf(fmaf(xcv, Dv, part), zs, acc);
        xcv = nxc; zs = nz; Tv = nT; Bv = nB; Cv = nC; r = rn;
    }
    if (lane == 0) g_ysum[dir][b*DIN + d] = acc;
}

// ---------------- head: mean -> out_proj (both dirs) -> fc ------------------
__global__ void head_kernel(const float* __restrict__ fow, const float* __restrict__ bow,
                            const float* __restrict__ fcw, const float* __restrict__ fcb,
                            float* __restrict__ out) {
    int b = blockIdx.x;
    __shared__ float ys0[DIN], ys1[DIN], o[DIMV];
    int t = threadIdx.x;                               // 192
    for (int i = t; i < DIN; i += DIMV) {
        ys0[i] = g_ysum[0][b*DIN + i] * (1.0f/SEQL);
        ys1[i] = g_ysum[1][b*DIN + i] * (1.0f/SEQL);
    }
    __syncthreads();
    float acc = 0.f;
    #pragma unroll 4
    for (int di = 0; di < DIN; di++)
        acc = fmaf(ys0[di], fow[(size_t)t*DIN + di], fmaf(ys1[di], bow[(size_t)t*DIN + di], acc));
    o[t] = acc;
    __syncthreads();
    if (t < 4) {
        float s = fcb[t];
        #pragma unroll 4
        for (int d = 0; d < DIMV; d++) s = fmaf(o[d], fcw[t*DIMV + d], s);
        out[b*4 + t] = s;
    }
}

// ---------------- launch ----------------------------------------------------
extern "C" void kernel_launch(void* const* d_in, const int* in_sizes, int n_in,
                              void* d_out, int out_size) {
    (void)in_sizes; (void)n_in; (void)out_size;
    const float* x       = (const float*)d_in[0];
    const float* patch_w = (const float*)d_in[1];
    const float* patch_b = (const float*)d_in[2];
    const float* ln_g    = (const float*)d_in[3];
    const float* ln_b    = (const float*)d_in[4];
    const float* fc_w    = (const float*)d_in[5];
    const float* fc_b    = (const float*)d_in[6];
    // per-direction params: in_w, conv_w, conv_b, xproj_w, dt_w, dt_b, A_log, D, out_w
    const float* P[2][9];
    for (int dir = 0; dir < 2; dir++)
        for (int i = 0; i < 9; i++)
            P[dir][i] = (const float*)d_in[7 + dir*9 + i];

    float *tok, *xi, *zs, *xc, *proj;
    cudaGetSymbolAddress((void**)&tok,  g_tok);
    cudaGetSymbolAddress((void**)&xi,   g_xi);
    cudaGetSymbolAddress((void**)&zs,   g_zs);
    cudaGetSymbolAddress((void**)&xc,   g_xc);
    cudaGetSymbolAddress((void**)&proj, g_proj);

    cudaFuncSetAttribute(gemm_fp16_kernel<true,false>,
                         cudaFuncAttributeMaxDynamicSharedMemorySize, GEMM_SMEM);
    cudaFuncSetAttribute(gemm_fp16_kernel<false,false>,
                         cudaFuncAttributeMaxDynamicSharedMemorySize, GEMM_SMEM);
    cudaFuncSetAttribute(gemm_fp16_kernel<false,true>,
                         cudaFuncAttributeMaxDynamicSharedMemorySize, GEMM_SMEM);

    // 1. patch embed GEMM with implicit im2col (bias folded into LN)
    gemm_fp16_kernel<true,false><<<dim3(DIMV/NT, MTOK/MT, 1), 256, GEMM_SMEM>>>(
        x, x, patch_w, patch_w, tok, tok, tok, tok, 768, DIMV, DIMV);
    // 2. layernorm in place (adds patch_b first)
    ln_kernel<<<MTOK/8, 256>>>(tok, patch_b, ln_g, ln_b);
    // 3. in-projection, both dirs; x -> g_xi raw, z -> g_zs silu'd in epilogue
    gemm_fp16_kernel<false,true><<<dim3((2*DIN)/NT, MTOK/MT, 2), 256, GEMM_SMEM>>>(
        tok, tok, P[0][0], P[1][0],
        xi, xi + (size_t)MTOK*DIN,
        zs, zs + (size_t)MTOK*DIN, DIMV, 2*DIN, DIN);
    // 4. conv + silu
    conv_silu_kernel<<<dim3(SEQL/16, BATCH, 2), 96>>>(P[0][1], P[0][2], P[1][1], P[1][2]);
    // 5. x-projection (dt_raw | B | C), weights zero-padded 44 -> 64 cols
    gemm_fp16_kernel<false,false><<<dim3(1, MTOK/MT, 2), 256, GEMM_SMEM>>>(
        xc, xc + (size_t)MTOK*DIN, P[0][3], P[1][3],
        proj, proj + (size_t)MTOK*NPROJP,
        proj, proj + (size_t)MTOK*NPROJP, DIN, 44, NPROJP);
    // 6. selective scan (dt fused), accumulating token-sum
    scan_kernel<<<(2*BATCH*DIN*4)/128, 128>>>(
        P[0][6], P[0][7], P[1][6], P[1][7],
        P[0][4], P[0][5], P[1][4], P[1][5]);
    // 7. head: mean-pool -> out_w (both dirs) -> fc
    head_kernel<<<BATCH, DIMV>>>(P[0][8], P[1][8], fc_w, fc_b, (float*)d_out);
}

// round 10
// speedup vs baseline: 1.8938x; 1.0462x over previous
#include <cuda_runtime.h>
#include <cuda_fp16.h>
#include <mma.h>
#include <cstdint>
#include <cstddef>

using namespace nvcuda;

// ---------------- problem constants ----------------
#define BATCH   32
#define SEQL    576                 // 24*24 tokens
#define MTOK    (BATCH*SEQL)        // 18432
#define DIMV    192
#define DIN     384                 // 2*DIM
#define DSTATE  16
#define DTRANK  12
#define NPROJP  64                  // padded proj row stride (real cols: 44)

// ---------------- scratch (device globals; no allocation) ----------------
__device__ float  g_tok [(size_t)MTOK * DIMV];            // fp32 (LN in place)
__device__ __half g_xi  [2][(size_t)MTOK * DIN];          // raw x (pre-conv), fp16
__device__ __half g_zs  [2][(size_t)MTOK * DIN];          // silu(z), fp16
__device__ __half g_xc  [2][(size_t)MTOK * DIN];          // silu(conv(x)), fp16
__device__ float  g_proj[2][(size_t)MTOK * NPROJP];       // [dt_raw|B|C|pad] fp32
__device__ float  g_ysum[2][BATCH * DIN];

// ---------------- fp16 WMMA GEMM -------------------------------------------
// C[M,Nout] = A[M,K] @ W[Nw,K]^T, rows of W beyond Nw are zero.
// Block tile 128x64x32, 8 warps (4m x 2n), warp tile 32x32 (2x2 m16n16k16).
// Double-buffered smem. blockIdx.z selects direction set 0/1.
// IMC:    implicit im2col of x[32,3,384,384] into A[MTOK,768].
// AHALF:  A is already __half (direct copy into smem, no conversion).
// ZSPLIT: output cols [0,DIN) -> Cx (half, raw); [DIN,2*DIN) -> Cz (half,
//         silu applied in fp32); both with row stride Nout(=DIN), via smem
//         staging epilogue. Otherwise C is fp32 store_matrix_sync.
#define MT 128
#define NT 64
#define KT 32
#define SBK 40                      // smem row stride in halfs (pad 32->40)
#define ASZ (MT*SBK)
#define BSZ (NT*SBK)
#define GEMM_SMEM 32768             // max(pipeline 30720, epilogue stage 32768)

#define CVTSTOREH(dst, off, v) do {                                           \
    __half2 h0_ = __floats2half2_rn((v).x, (v).y);                            \
    __half2 h1_ = __floats2half2_rn((v).z, (v).w);                            \
    *(__half2*)&(dst)[(off)]     = h0_;                                       \
    *(__half2*)&(dst)[(off) + 2] = h1_;                                       \
} while (0)

template<bool IMC, bool AHALF, bool ZSPLIT>
__global__ __launch_bounds__(256) void gemm_fp16_kernel(
    const void* __restrict__ A0v, const void* __restrict__ A1v,
    const float* __restrict__ W0, const float* __restrict__ W1,
    void* __restrict__ Cx0, void* __restrict__ Cx1,
    void* __restrict__ Cz0, void* __restrict__ Cz1,
    int K, int Nw, int Nout)
{
    extern __shared__ __half sm[];
    __half* As = sm;                    // [2][MT][SBK]
    __half* Bs = sm + 2*ASZ;            // [2][NT][SBK]

    const void* Av = blockIdx.z ? A1v : A0v;
    const float* W = blockIdx.z ? W1 : W0;
    void* Cx = blockIdx.z ? Cx1 : Cx0;
    void* Cz = blockIdx.z ? Cz1 : Cz0;

    const int tid  = threadIdx.x;
    const int warp = tid >> 5;
    const int lane = tid & 31;
    const int wm   = warp >> 1;      // 0..3 -> m offset wm*32
    const int wn   = warp & 1;       // 0..1 -> n offset wn*32
    const int m0 = blockIdx.y * MT;
    const int n0 = blockIdx.x * NT;
    const int ar = tid >> 3, akc = (tid & 7) * 4;

    int rb[4];
    if (IMC) {
        #pragma unroll
        for (int i = 0; i < 4; i++) {
            int tok = m0 + ar + i*32;
            int b = tok / SEQL, rl = tok - b*SEQL;
            int hp = rl / 24, wp = rl - hp*24;
            rb[i] = b*442368 + hp*6144 + wp*16;   // 3*384*384, 16*384
        }
    }

    wmma::fragment<wmma::accumulator,16,16,16,float> acc[2][2];
    #pragma unroll
    for (int i = 0; i < 2; i++)
        #pragma unroll
        for (int j = 0; j < 2; j++)
            wmma::fill_fragment(acc[i][j], 0.0f);

    float4 pa[4];
    uint2  pah[4];
    float4 pb[2];

    #define LOADT(k0)  do {                                                   \
        if (IMC) {                                                            \
            const float* Af = (const float*)Av;                               \
            int k_ = (k0) + akc;                                              \
            int c_ = k_ >> 8, pq_ = k_ & 255;                                 \
            int koff_ = c_*147456 + (pq_ >> 4)*384 + (pq_ & 15);              \
            _Pragma("unroll")                                                 \
            for (int i = 0; i < 4; i++)                                       \
                pa[i] = *(const float4*)&Af[rb[i] + koff_];                   \
        } else if (AHALF) {                                                   \
            const __half* Ah = (const __half*)Av;                             \
            _Pragma("unroll")                                                 \
            for (int i = 0; i < 4; i++)                                       \
                pah[i] = *(const uint2*)&Ah[(size_t)(m0 + ar + i*32)*K + (k0) + akc]; \
        } else {                                                              \
            const float* Af = (const float*)Av;                               \
            _Pragma("unroll")                                                 \
            for (int i = 0; i < 4; i++)                                       \
                pa[i] = *(const float4*)&Af[(size_t)(m0 + ar + i*32)*K + (k0) + akc]; \
        }                                                                     \
        _Pragma("unroll")                                                     \
        for (int i = 0; i < 2; i++) {                                         \
            int r_ = ar + i*32;                                               \
            pb[i] = (n0 + r_ < Nw)                                            \
                ? *(const float4*)&W[(size_t)(n0 + r_)*K + (k0) + akc]        \
                : make_float4(0.f,0.f,0.f,0.f);                               \
        }                                                                     \
    } while (0)

    #define STORET(buf)  do {                                                 \
        _Pragma("unroll")                                                     \
        for (int i = 0; i < 4; i++) {                                         \
            int off_ = (buf)*ASZ + (ar + i*32)*SBK + akc;                     \
            if (AHALF) *(uint2*)&As[off_] = pah[i];                           \
            else       CVTSTOREH(As, off_, pa[i]);                            \
        }                                                                     \
        _Pragma("unroll")                                                     \
        for (int i = 0; i < 2; i++)                                           \
            CVTSTOREH(Bs, (buf)*BSZ + (ar + i*32)*SBK + akc, pb[i]);          \
    } while (0)

    LOADT(0);
    STORET(0);
    __syncthreads();

    int buf = 0;
    for (int k0 = 0; k0 < K; k0 += KT) {
        const bool more = (k0 + KT) < K;
        if (more) LOADT(k0 + KT);
        #pragma unroll
        for (int kk = 0; kk < KT; kk += 16) {
            wmma::fragment<wmma::matrix_b,16,16,16,__half,wmma::col_major> bf[2];
            #pragma unroll
            for (int j = 0; j < 2; j++)
                wmma::load_matrix_sync(bf[j], &Bs[buf*BSZ + (wn*32 + j*16)*SBK + kk], SBK);
            #pragma unroll
            for (int i = 0; i < 2; i++) {
                wmma::fragment<wmma::matrix_a,16,16,16,__half,wmma::row_major> af;
                wmma::load_matrix_sync(af, &As[buf*ASZ + (wm*32 + i*16)*SBK + kk], SBK);
                #pragma unroll
                for (int j = 0; j < 2; j++)
                    wmma::mma_sync(acc[i][j], af, bf[j], acc[i][j]);
            }
        }
        if (more) STORET(buf ^ 1);
        __syncthreads();
        buf ^= 1;
    }

    if (ZSPLIT) {
        // stage fp32 accumulators in smem, convert to half (silu on z-half)
        __syncthreads();
        float* stage = reinterpret_cast<float*>(sm) + warp * 1024;  // 32x32
        #pragma unroll
        for (int i = 0; i < 2; i++)
            #pragma unroll
            for (int j = 0; j < 2; j++)
                wmma::store_matrix_sync(&stage[i*16*32 + j*16], acc[i][j], 32,
                                        wmma::mem_row_major);
        __syncwarp();
        int nbase = n0 + wn*32;
        bool isz = nbase >= DIN;
        __half* Cd = reinterpret_cast<__half*>(isz ? Cz : Cx);
        int nc0 = (isz ? nbase - DIN : nbase) + (lane & 3) * 8;
        #pragma unroll
        for (int r4 = 0; r4 < 4; r4++) {
            int row = r4*8 + (lane >> 2);
            const float* src = &stage[row*32 + (lane & 3)*8];
            __half2 h[4];
            #pragma unroll
            for (int c = 0; c < 4; c++) {
                float v0 = src[c*2], v1 = src[c*2 + 1];
                if (isz) {
                    v0 = v0 * __frcp_rn(1.0f + __expf(-v0));
                    v1 = v1 * __frcp_rn(1.0f + __expf(-v1));
                }
                h[c] = __floats2half2_rn(v0, v1);
            }
            *(uint4*)&Cd[(size_t)(m0 + wm*32 + row)*Nout + nc0] = *(uint4*)h;
        }
    } else {
        float* C = (float*)Cx;
        #pragma unroll
        for (int i = 0; i < 2; i++)
            #pragma unroll
            for (int j = 0; j < 2; j++)
                wmma::store_matrix_sync(
                    &C[(size_t)(m0 + wm*32 + i*16)*Nout + n0 + wn*32 + j*16],
                    acc[i][j], Nout, wmma::mem_row_major);
    }
    #undef LOADT
    #undef STORET
}

// ---------------- LayerNorm over DIM=192 (patch bias folded in) -------------
__global__ void ln_kernel(float* __restrict__ tok, const float* __restrict__ pb,
                          const float* __restrict__ g, const float* __restrict__ b) {
    int row  = blockIdx.x * 8 + (threadIdx.x >> 5);
    int lane = threadIdx.x & 31;
    float* p = tok + (size_t)row * DIMV;
    float v[6]; float s = 0.f;
    #pragma unroll
    for (int i = 0; i < 6; i++) {
        int c = lane + i*32;
        v[i] = p[c] + pb[c];
        s += v[i];
    }
    #pragma unroll
    for (int o = 16; o; o >>= 1) s += __shfl_xor_sync(0xffffffffu, s, o);
    float mu = s * (1.0f/192.0f);
    float q = 0.f;
    #pragma unroll
    for (int i = 0; i < 6; i++) { float d = v[i] - mu; q = fmaf(d, d, q); }
    #pragma unroll
    for (int o = 16; o; o >>= 1) q += __shfl_xor_sync(0xffffffffu, q, o);
    float rstd = rsqrtf(q * (1.0f/192.0f) + 1e-5f);
    #pragma unroll
    for (int i = 0; i < 6; i++) {
        int c = lane + i*32;
        p[c] = (v[i] - mu) * rstd * g[c] + b[c];
    }
}

// ---------------- conv + silu (half in/out, fp32 math) ----------------------
__device__ __forceinline__ float4 h4tof4(uint2 u) {
    float2 a = __half22float2(*(__half2*)&u.x);
    float2 b = __half22float2(*(__half2*)&u.y);
    return make_float4(a.x, a.y, b.x, b.y);
}

__global__ __launch_bounds__(96) void conv_silu_kernel(
    const float* __restrict__ cwf, const float* __restrict__ cbf,
    const float* __restrict__ cwb, const float* __restrict__ cbb)
{
    const int dir = blockIdx.z;
    const int b   = blockIdx.y;
    const int l0  = blockIdx.x * 16;
    const int d   = threadIdx.x * 4;          // 0..380
    const float* cw = dir ? cwb : cwf;
    const float* cb = dir ? cbb : cbf;

    float4 a0 = *(const float4*)&cw[(d+0)*4];
    float4 a1 = *(const float4*)&cw[(d+1)*4];
    float4 a2 = *(const float4*)&cw[(d+2)*4];
    float4 a3 = *(const float4*)&cw[(d+3)*4];
    float4 t0 = make_float4(a0.x, a1.x, a2.x, a3.x);
    float4 t1 = make_float4(a0.y, a1.y, a2.y, a3.y);
    float4 t2 = make_float4(a0.z, a1.z, a2.z, a3.z);
    float4 t3 = make_float4(a0.w, a1.w, a2.w, a3.w);
    float4 bias = *(const float4*)&cb[d];

    const __half* xi = g_xi[dir];
    __half* xc = g_xc[dir];
    const int s  = dir ? -1 : 1;
    int l = dir ? (l0 + 15) : l0;

    #define LDX(ll) ((unsigned)(ll) < SEQL                                     \
        ? h4tof4(*(const uint2*)&xi[((size_t)(b*SEQL + (ll)))*DIN + d])        \
        : make_float4(0.f,0.f,0.f,0.f))

    float4 w0 = LDX(l - 3*s);
    float4 w1 = LDX(l - 2*s);
    float4 w2 = LDX(l - 1*s);

    #pragma unroll 4
    for (int i = 0; i < 16; i++, l += s) {
        float4 w3 = h4tof4(*(const uint2*)&xi[(size_t)(b*SEQL + l)*DIN + d]);
        float4 r;
        r.x = fmaf(t3.x, w3.x, fmaf(t2.x, w2.x, fmaf(t1.x, w1.x, fmaf(t0.x, w0.x, bias.x))));
        r.y = fmaf(t3.y, w3.y, fmaf(t2.y, w2.y, fmaf(t1.y, w1.y, fmaf(t0.y, w0.y, bias.y))));
        r.z = fmaf(t3.z, w3.z, fmaf(t2.z, w2.z, fmaf(t1.z, w1.z, fmaf(t0.z, w0.z, bias.z))));
        r.w = fmaf(t3.w, w3.w, fmaf(t2.w, w2.w, fmaf(t1.w, w1.w, fmaf(t0.w, w0.w, bias.w))));
        r.x = r.x * __frcp_rn(1.0f + __expf(-r.x));
        r.y = r.y * __frcp_rn(1.0f + __expf(-r.y));
        r.z = r.z * __frcp_rn(1.0f + __expf(-r.z));
        r.w = r.w * __frcp_rn(1.0f + __expf(-r.w));
        uint2 o;
        *(__half2*)&o.x = __floats2half2_rn(r.x, r.y);
        *(__half2*)&o.y = __floats2half2_rn(r.z, r.w);
        *(uint2*)&xc[(size_t)(b*SEQL + l)*DIN + d] = o;
        w0 = w1; w1 = w2; w2 = w3;
    }
    #undef LDX
}

// ---------------- selective scan (dt fused); accumulates sum over L --------
__global__ __launch_bounds__(128) void scan_kernel(
    const float* __restrict__ Alf, const float* __restrict__ Df,
    const float* __restrict__ Alb, const float* __restrict__ Db,
    const float* __restrict__ dtwf, const float* __restrict__ dtbf,
    const float* __restrict__ dtwb, const float* __restrict__ dtbb)
{
    int gid  = (blockIdx.x * 128 + threadIdx.x) >> 2;
    int lane = threadIdx.x & 3;
    if (gid >= 2 * BATCH * DIN) return;
    int dir = gid >= BATCH * DIN;
    int rem = gid - dir * BATCH * DIN;
    int b = rem / DIN, d = rem - b * DIN;
    const float* Alog = dir ? Alb : Alf;
    float Dv = (dir ? Db : Df)[d];
    float a0 = -__expf(Alog[d*DSTATE + lane*4 + 0]);
    float a1 = -__expf(Alog[d*DSTATE + lane*4 + 1]);
    float a2 = -__expf(Alog[d*DSTATE + lane*4 + 2]);
    float a3 = -__expf(Alog[d*DSTATE + lane*4 + 3]);
    const float* dtw = dir ? dtwb : dtwf;
    float dtbias = (dir ? dtbb : dtbf)[d];
    float w0dt = 0.f, w1dt = 0.f, w2dt = 0.f, w3dt = 0.f;
    if (lane < 3) {
        w0dt = dtw[d*DTRANK + lane*4 + 0];
        w1dt = dtw[d*DTRANK + lane*4 + 1];
        w2dt = dtw[d*DTRANK + lane*4 + 2];
        w3dt = dtw[d*DTRANK + lane*4 + 3];
    }
    const __half* xcp = g_xc[dir];
    const __half* zp  = g_zs[dir];
    const float*  pp  = g_proj[dir];
    float h0=0.f,h1=0.f,h2=0.f,h3=0.f, acc=0.f;
    int r    = b*SEQL + (dir ? SEQL - 1 : 0);
    int step = dir ? -1 : 1;

    float  xcv = __half2float(xcp[(size_t)r*DIN + d]);
    float  zs  = __half2float(zp[(size_t)r*DIN + d]);
    float4 Tv = *(const float4*)&pp[(size_t)r*NPROJP + lane*4];
    float4 Bv = *(const float4*)&pp[(size_t)r*NPROJP + DTRANK + lane*4];
    float4 Cv = *(const float4*)&pp[(size_t)r*NPROJP + DTRANK + DSTATE + lane*4];

    for (int t = 0; t < SEQL; t++) {
        int rn = r + step;
        float nxc = 0.f, nz = 0.f;
        float4 nT = Tv, nB = Bv, nC = Cv;
        if (t + 1 < SEQL) {
            size_t rdn = (size_t)rn * DIN + d;
            nxc = __half2float(xcp[rdn]);
            nz  = __half2float(zp[rdn]);
            nT = *(const float4*)&pp[(size_t)rn*NPROJP + lane*4];
            nB = *(const float4*)&pp[(size_t)rn*NPROJP + DTRANK + lane*4];
            nC = *(const float4*)&pp[(size_t)rn*NPROJP + DTRANK + DSTATE + lane*4];
        }
        float dp = fmaf(w3dt, Tv.w, fmaf(w2dt, Tv.z, fmaf(w1dt, Tv.y, w0dt*Tv.x)));
        dp += __shfl_xor_sync(0xffffffffu, dp, 1);
        dp += __shfl_xor_sync(0xffffffffu, dp, 2);
        dp += dtbias;
        float dtv = fmaxf(dp, 0.0f) + __logf(1.0f + __expf(-fabsf(dp)));
        float dtx = dtv * xcv;
        h0 = fmaf(__expf(dtv*a0), h0, dtx*Bv.x);
        h1 = fmaf(__expf(dtv*a1), h1, dtx*Bv.y);
        h2 = fmaf(__expf(dtv*a2), h2, dtx*Bv.z);
        h3 = fmaf(__expf(dtv*a3), h3, dtx*Bv.w);
        float part = fmaf(h0,Cv.x, fmaf(h1,Cv.y, fmaf(h2,Cv.z, h3*Cv.w)));
        part += __shfl_xor_sync(0xffffffffu, part, 1);
        part += __shfl_xor_sync(0xffffffffu, part, 2);
        acc = fmaf(fmaf(xcv, Dv, part), zs, acc);
        xcv = nxc; zs = nz; Tv = nT; Bv = nB; Cv = nC; r = rn;
    }
    if (lane == 0) g_ysum[dir][b*DIN + d] = acc;
}

// ---------------- head: mean -> out_proj (both dirs) -> fc ------------------
__global__ void head_kernel(const float* __restrict__ fow, const float* __restrict__ bow,
                            const float* __restrict__ fcw, const float* __restrict__ fcb,
                            float* __restrict__ out) {
    int b = blockIdx.x;
    __shared__ float ys0[DIN], ys1[DIN], o[DIMV];
    int t = threadIdx.x;                               // 192
    for (int i = t; i < DIN; i += DIMV) {
        ys0[i] = g_ysum[0][b*DIN + i] * (1.0f/SEQL);
        ys1[i] = g_ysum[1][b*DIN + i] * (1.0f/SEQL);
    }
    __syncthreads();
    float acc = 0.f;
    #pragma unroll 4
    for (int di = 0; di < DIN; di++)
        acc = fmaf(ys0[di], fow[(size_t)t*DIN + di], fmaf(ys1[di], bow[(size_t)t*DIN + di], acc));
    o[t] = acc;
    __syncthreads();
    if (t < 4) {
        float s = fcb[t];
        #pragma unroll 4
        for (int d = 0; d < DIMV; d++) s = fmaf(o[d], fcw[t*DIMV + d], s);
        out[b*4 + t] = s;
    }
}

// ---------------- launch ----------------------------------------------------
extern "C" void kernel_launch(void* const* d_in, const int* in_sizes, int n_in,
                              void* d_out, int out_size) {
    (void)in_sizes; (void)n_in; (void)out_size;
    const float* x       = (const float*)d_in[0];
    const float* patch_w = (const float*)d_in[1];
    const float* patch_b = (const float*)d_in[2];
    const float* ln_g    = (const float*)d_in[3];
    const float* ln_b    = (const float*)d_in[4];
    const float* fc_w    = (const float*)d_in[5];
    const float* fc_b    = (const float*)d_in[6];
    // per-direction params: in_w, conv_w, conv_b, xproj_w, dt_w, dt_b, A_log, D, out_w
    const float* P[2][9];
    for (int dir = 0; dir < 2; dir++)
        for (int i = 0; i < 9; i++)
            P[dir][i] = (const float*)d_in[7 + dir*9 + i];

    float *tok, *proj;
    __half *xi, *zs, *xc;
    cudaGetSymbolAddress((void**)&tok,  g_tok);
    cudaGetSymbolAddress((void**)&xi,   g_xi);
    cudaGetSymbolAddress((void**)&zs,   g_zs);
    cudaGetSymbolAddress((void**)&xc,   g_xc);
    cudaGetSymbolAddress((void**)&proj, g_proj);

    cudaFuncSetAttribute(gemm_fp16_kernel<true,false,false>,
                         cudaFuncAttributeMaxDynamicSharedMemorySize, GEMM_SMEM);
    cudaFuncSetAttribute(gemm_fp16_kernel<false,false,true>,
                         cudaFuncAttributeMaxDynamicSharedMemorySize, GEMM_SMEM);
    cudaFuncSetAttribute(gemm_fp16_kernel<false,true,false>,
                         cudaFuncAttributeMaxDynamicSharedMemorySize, GEMM_SMEM);

    // 1. patch embed GEMM with implicit im2col (bias folded into LN)
    gemm_fp16_kernel<true,false,false><<<dim3(DIMV/NT, MTOK/MT, 1), 256, GEMM_SMEM>>>(
        x, x, patch_w, patch_w, tok, tok, tok, tok, 768, DIMV, DIMV);
    // 2. layernorm in place (adds patch_b first)
    ln_kernel<<<MTOK/8, 256>>>(tok, patch_b, ln_g, ln_b);
    // 3. in-projection, both dirs; x -> g_xi (half), z -> g_zs (silu, half)
    gemm_fp16_kernel<false,false,true><<<dim3((2*DIN)/NT, MTOK/MT, 2), 256, GEMM_SMEM>>>(
        tok, tok, P[0][0], P[1][0],
        xi, xi + (size_t)MTOK*DIN,
        zs, zs + (size_t)MTOK*DIN, DIMV, 2*DIN, DIN);
    // 4. conv + silu (half -> half)
    conv_silu_kernel<<<dim3(SEQL/16, BATCH, 2), 96>>>(P[0][1], P[0][2], P[1][1], P[1][2]);
    // 5. x-projection (dt_raw | B | C); A half, weights padded 44 -> 64 cols
    gemm_fp16_kernel<false,true,false><<<dim3(1, MTOK/MT, 2), 256, GEMM_SMEM>>>(
        xc, xc + (size_t)MTOK*DIN, P[0][3], P[1][3],
        proj, proj + (size_t)MTOK*NPROJP,
        proj, proj + (size_t)MTOK*NPROJP, DIN, 44, NPROJP);
    // 6. selective scan (dt fused), accumulating token-sum
    scan_kernel<<<(2*BATCH*DIN*4)/128, 128>>>(
        P[0][6], P[0][7], P[1][6], P[1][7],
        P[0][4], P[0][5], P[1][4], P[1][5]);
    // 7. head: mean-pool -> out_w (both dirs) -> fc
    head_kernel<<<BATCH, DIMV>>>(P[0][8], P[1][8], fc_w, fc_b, (float*)d_out);
}

// round 12
// speedup vs baseline: 2.2250x; 1.1749x over previous
#include <cuda_runtime.h>
#include <cuda_fp16.h>
#include <mma.h>
#include <cstdint>
#include <cstddef>

using namespace nvcuda;

// ---------------- problem constants ----------------
#define BATCH   32
#define SEQL    576                 // 24*24 tokens
#define MTOK    (BATCH*SEQL)        // 18432
#define DIMV    192
#define DIN     384                 // 2*DIM
#define DSTATE  16
#define DTRANK  12
#define NPROJP  64                  // padded proj row stride (real cols: 44)
#define CH      4                   // scan chunks
#define CHL     (SEQL/CH)           // 144 tokens per chunk

// ---------------- scratch (device globals; no allocation) ----------------
__device__ float  g_tok [(size_t)MTOK * DIMV];            // fp32 (LN in place)
__device__ __half g_xi  [2][(size_t)MTOK * DIN];          // raw x (pre-conv)
__device__ __half g_zs  [2][(size_t)MTOK * DIN];          // silu(z)
__device__ __half g_xc  [2][(size_t)MTOK * DIN];          // silu(conv(x))
__device__ float  g_proj[2][(size_t)MTOK * NPROJP];       // [dt_raw|B|C|pad]
// per-chunk partials: part = (((dir*B+b)*CH+c)*DIN+d), float4 per lane
#define NPART (2*BATCH*CH*DIN)
__device__ float4 g_hout[NPART*4];
__device__ float4 g_pf  [NPART*4];
__device__ float4 g_w   [NPART*4];
__device__ float  g_pacc[NPART];
__device__ float  g_ysum[2][BATCH * DIN];

// ---------------- fp16 WMMA GEMM -------------------------------------------
#define MT 128
#define NT 64
#define KT 32
#define SBK 40
#define ASZ (MT*SBK)
#define BSZ (NT*SBK)
#define GEMM_SMEM 32768

#define CVTSTOREH(dst, off, v) do {                                           \
    __half2 h0_ = __floats2half2_rn((v).x, (v).y);                            \
    __half2 h1_ = __floats2half2_rn((v).z, (v).w);                            \
    *(__half2*)&(dst)[(off)]     = h0_;                                       \
    *(__half2*)&(dst)[(off) + 2] = h1_;                                       \
} while (0)

template<bool IMC, bool AHALF, bool ZSPLIT>
__global__ __launch_bounds__(256) void gemm_fp16_kernel(
    const void* __restrict__ A0v, const void* __restrict__ A1v,
    const float* __restrict__ W0, const float* __restrict__ W1,
    void* __restrict__ Cx0, void* __restrict__ Cx1,
    void* __restrict__ Cz0, void* __restrict__ Cz1,
    int K, int Nw, int Nout)
{
    extern __shared__ __half sm[];
    __half* As = sm;
    __half* Bs = sm + 2*ASZ;

    const void* Av = blockIdx.z ? A1v : A0v;
    const float* W = blockIdx.z ? W1 : W0;
    void* Cx = blockIdx.z ? Cx1 : Cx0;
    void* Cz = blockIdx.z ? Cz1 : Cz0;

    const int tid  = threadIdx.x;
    const int warp = tid >> 5;
    const int lane = tid & 31;
    const int wm   = warp >> 1;
    const int wn   = warp & 1;
    const int m0 = blockIdx.y * MT;
    const int n0 = blockIdx.x * NT;
    const int ar = tid >> 3, akc = (tid & 7) * 4;

    int rb[4];
    if (IMC) {
        #pragma unroll
        for (int i = 0; i < 4; i++) {
            int tok = m0 + ar + i*32;
            int b = tok / SEQL, rl = tok - b*SEQL;
            int hp = rl / 24, wp = rl - hp*24;
            rb[i] = b*442368 + hp*6144 + wp*16;
        }
    }

    wmma::fragment<wmma::accumulator,16,16,16,float> acc[2][2];
    #pragma unroll
    for (int i = 0; i < 2; i++)
        #pragma unroll
        for (int j = 0; j < 2; j++)
            wmma::fill_fragment(acc[i][j], 0.0f);

    float4 pa[4];
    uint2  pah[4];
    float4 pb[2];

    #define LOADT(k0)  do {                                                   \
        if (IMC) {                                                            \
            const float* Af = (const float*)Av;                               \
            int k_ = (k0) + akc;                                              \
            int c_ = k_ >> 8, pq_ = k_ & 255;                                 \
            int koff_ = c_*147456 + (pq_ >> 4)*384 + (pq_ & 15);              \
            _Pragma("unroll")                                                 \
            for (int i = 0; i < 4; i++)                                       \
                pa[i] = *(const float4*)&Af[rb[i] + koff_];                   \
        } else if (AHALF) {                                                   \
            const __half* Ah = (const __half*)Av;                             \
            _Pragma("unroll")                                                 \
            for (int i = 0; i < 4; i++)                                       \
                pah[i] = *(const uint2*)&Ah[(size_t)(m0 + ar + i*32)*K + (k0) + akc]; \
        } else {                                                              \
            const float* Af = (const float*)Av;                               \
            _Pragma("unroll")                                                 \
            for (int i = 0; i < 4; i++)                                       \
                pa[i] = *(const float4*)&Af[(size_t)(m0 + ar + i*32)*K + (k0) + akc]; \
        }                                                                     \
        _Pragma("unroll")                                                     \
        for (int i = 0; i < 2; i++) {                                         \
            int r_ = ar + i*32;                                               \
            pb[i] = (n0 + r_ < Nw)                                            \
                ? *(const float4*)&W[(size_t)(n0 + r_)*K + (k0) + akc]        \
                : make_float4(0.f,0.f,0.f,0.f);                               \
        }                                                                     \
    } while (0)

    #define STORET(buf)  do {                                                 \
        _Pragma("unroll")                                                     \
        for (int i = 0; i < 4; i++) {                                         \
            int off_ = (buf)*ASZ + (ar + i*32)*SBK + akc;                     \
            if (AHALF) *(uint2*)&As[off_] = pah[i];                           \
            else       CVTSTOREH(As, off_, pa[i]);                            \
        }                                                                     \
        _Pragma("unroll")                                                     \
        for (int i = 0; i < 2; i++)                                           \
            CVTSTOREH(Bs, (buf)*BSZ + (ar + i*32)*SBK + akc, pb[i]);          \
    } while (0)

    LOADT(0);
    STORET(0);
    __syncthreads();

    int buf = 0;
    for (int k0 = 0; k0 < K; k0 += KT) {
        const bool more = (k0 + KT) < K;
        if (more) LOADT(k0 + KT);
        #pragma unroll
        for (int kk = 0; kk < KT; kk += 16) {
            wmma::fragment<wmma::matrix_b,16,16,16,__half,wmma::col_major> bf[2];
            #pragma unroll
            for (int j = 0; j < 2; j++)
                wmma::load_matrix_sync(bf[j], &Bs[buf*BSZ + (wn*32 + j*16)*SBK + kk], SBK);
            #pragma unroll
            for (int i = 0; i < 2; i++) {
                wmma::fragment<wmma::matrix_a,16,16,16,__half,wmma::row_major> af;
                wmma::load_matrix_sync(af, &As[buf*ASZ + (wm*32 + i*16)*SBK + kk], SBK);
                #pragma unroll
                for (int j = 0; j < 2; j++)
                    wmma::mma_sync(acc[i][j], af, bf[j], acc[i][j]);
            }
        }
        if (more) STORET(buf ^ 1);
        __syncthreads();
        buf ^= 1;
    }

    if (ZSPLIT) {
        __syncthreads();
        float* stage = reinterpret_cast<float*>(sm) + warp * 1024;
        #pragma unroll
        for (int i = 0; i < 2; i++)
            #pragma unroll
            for (int j = 0; j < 2; j++)
                wmma::store_matrix_sync(&stage[i*16*32 + j*16], acc[i][j], 32,
                                        wmma::mem_row_major);
        __syncwarp();
        int nbase = n0 + wn*32;
        bool isz = nbase >= DIN;
        __half* Cd = reinterpret_cast<__half*>(isz ? Cz : Cx);
        int nc0 = (isz ? nbase - DIN : nbase) + (lane & 3) * 8;
        #pragma unroll
        for (int r4 = 0; r4 < 4; r4++) {
            int row = r4*8 + (lane >> 2);
            const float* src = &stage[row*32 + (lane & 3)*8];
            __half2 h[4];
            #pragma unroll
            for (int c = 0; c < 4; c++) {
                float v0 = src[c*2], v1 = src[c*2 + 1];
                if (isz) {
                    v0 = v0 * __frcp_rn(1.0f + __expf(-v0));
                    v1 = v1 * __frcp_rn(1.0f + __expf(-v1));
                }
                h[c] = __floats2half2_rn(v0, v1);
            }
            *(uint4*)&Cd[(size_t)(m0 + wm*32 + row)*Nout + nc0] = *(uint4*)h;
        }
    } else {
        float* C = (float*)Cx;
        #pragma unroll
        for (int i = 0; i < 2; i++)
            #pragma unroll
            for (int j = 0; j < 2; j++)
                wmma::store_matrix_sync(
                    &C[(size_t)(m0 + wm*32 + i*16)*Nout + n0 + wn*32 + j*16],
                    acc[i][j], Nout, wmma::mem_row_major);
    }
    #undef LOADT
    #undef STORET
}

// ---------------- LayerNorm over DIM=192 (patch bias folded in) -------------
__global__ void ln_kernel(float* __restrict__ tok, const float* __restrict__ pb,
                          const float* __restrict__ g, const float* __restrict__ b) {
    int row  = blockIdx.x * 8 + (threadIdx.x >> 5);
    int lane = threadIdx.x & 31;
    float* p = tok + (size_t)row * DIMV;
    float v[6]; float s = 0.f;
    #pragma unroll
    for (int i = 0; i < 6; i++) {
        int c = lane + i*32;
        v[i] = p[c] + pb[c];
        s += v[i];
    }
    #pragma unroll
    for (int o = 16; o; o >>= 1) s += __shfl_xor_sync(0xffffffffu, s, o);
    float mu = s * (1.0f/192.0f);
    float q = 0.f;
    #pragma unroll
    for (int i = 0; i < 6; i++) { float d = v[i] - mu; q = fmaf(d, d, q); }
    #pragma unroll
    for (int o = 16; o; o >>= 1) q += __shfl_xor_sync(0xffffffffu, q, o);
    float rstd = rsqrtf(q * (1.0f/192.0f) + 1e-5f);
    #pragma unroll
    for (int i = 0; i < 6; i++) {
        int c = lane + i*32;
        p[c] = (v[i] - mu) * rstd * g[c] + b[c];
    }
}

// ---------------- conv + silu (half in/out, fp32 math) ----------------------
__device__ __forceinline__ float4 h4tof4(uint2 u) {
    float2 a = __half22float2(*(__half2*)&u.x);
    float2 b = __half22float2(*(__half2*)&u.y);
    return make_float4(a.x, a.y, b.x, b.y);
}

__global__ __launch_bounds__(96) void conv_silu_kernel(
    const float* __restrict__ cwf, const float* __restrict__ cbf,
    const float* __restrict__ cwb, const float* __restrict__ cbb)
{
    const int dir = blockIdx.z;
    const int b   = blockIdx.y;
    const int l0  = blockIdx.x * 8;
    const int d   = threadIdx.x * 4;
    const float* cw = dir ? cwb : cwf;
    const float* cb = dir ? cbb : cbf;

    float4 a0 = *(const float4*)&cw[(d+0)*4];
    float4 a1 = *(const float4*)&cw[(d+1)*4];
    float4 a2 = *(const float4*)&cw[(d+2)*4];
    float4 a3 = *(const float4*)&cw[(d+3)*4];
    float4 t0 = make_float4(a0.x, a1.x, a2.x, a3.x);
    float4 t1 = make_float4(a0.y, a1.y, a2.y, a3.y);
    float4 t2 = make_float4(a0.z, a1.z, a2.z, a3.z);
    float4 t3 = make_float4(a0.w, a1.w, a2.w, a3.w);
    float4 bias = *(const float4*)&cb[d];

    const __half* xi = g_xi[dir];
    __half* xc = g_xc[dir];
    const int s  = dir ? -1 : 1;
    int l = dir ? (l0 + 7) : l0;

    #define LDX(ll) ((unsigned)(ll) < SEQL                                     \
        ? h4tof4(*(const uint2*)&xi[((size_t)(b*SEQL + (ll)))*DIN + d])        \
        : make_float4(0.f,0.f,0.f,0.f))

    float4 w0 = LDX(l - 3*s);
    float4 w1 = LDX(l - 2*s);
    float4 w2 = LDX(l - 1*s);

    #pragma unroll
    for (int i = 0; i < 8; i++, l += s) {
        float4 w3 = h4tof4(*(const uint2*)&xi[(size_t)(b*SEQL + l)*DIN + d]);
        float4 r;
        r.x = fmaf(t3.x, w3.x, fmaf(t2.x, w2.x, fmaf(t1.x, w1.x, fmaf(t0.x, w0.x, bias.x))));
        r.y = fmaf(t3.y, w3.y, fmaf(t2.y, w2.y, fmaf(t1.y, w1.y, fmaf(t0.y, w0.y, bias.y))));
        r.z = fmaf(t3.z, w3.z, fmaf(t2.z, w2.z, fmaf(t1.z, w1.z, fmaf(t0.z, w0.z, bias.z))));
        r.w = fmaf(t3.w, w3.w, fmaf(t2.w, w2.w, fmaf(t1.w, w1.w, fmaf(t0.w, w0.w, bias.w))));
        r.x = r.x * __frcp_rn(1.0f + __expf(-r.x));
        r.y = r.y * __frcp_rn(1.0f + __expf(-r.y));
        r.z = r.z * __frcp_rn(1.0f + __expf(-r.z));
        r.w = r.w * __frcp_rn(1.0f + __expf(-r.w));
        uint2 o;
        *(__half2*)&o.x = __floats2half2_rn(r.x, r.y);
        *(__half2*)&o.y = __floats2half2_rn(r.z, r.w);
        *(uint2*)&xc[(size_t)(b*SEQL + l)*DIN + d] = o;
        w0 = w1; w1 = w2; w2 = w3;
    }
    #undef LDX
}

// ---------------- scan part: chunk-local scan with smem-staged proj ---------
// CTA = (dseg, chunk, dir*b): 256 threads = 64 d-groups of 4 lanes.
// Stages the chunk's 144 proj rows (48 floats each) in smem once.
// Computes with h_in = 0: h_loc, P (cumulative decay), w = sum zs*C*P,
// acc_local = sum zs*(C.h_loc + xc*D). Exact chunked linear recurrence.
__global__ __launch_bounds__(256) void scan_part_kernel(
    const float* __restrict__ Alf, const float* __restrict__ Df,
    const float* __restrict__ Alb, const float* __restrict__ Db,
    const float* __restrict__ dtwf, const float* __restrict__ dtbf,
    const float* __restrict__ dtwb, const float* __restrict__ dtbb)
{
    __shared__ float sproj[CHL][48];
    const int tid  = threadIdx.x;
    const int lane = tid & 3;
    const int c    = blockIdx.y;
    const int zz   = blockIdx.z;
    const int dir  = zz / BATCH;
    const int b    = zz - dir*BATCH;
    const int d    = blockIdx.x * 64 + (tid >> 2);
    const int step = dir ? -1 : 1;
    const int r0   = b*SEQL + (dir ? (SEQL - 1 - c*CHL) : c*CHL);

    // stage proj rows for this chunk (scan order)
    const float* pp = g_proj[dir];
    for (int idx = tid; idx < CHL*12; idx += 256) {
        int row = idx / 12, q = idx - row*12;
        int rr = r0 + step*row;
        *(float4*)&sproj[row][q*4] = *(const float4*)&pp[(size_t)rr*NPROJP + q*4];
    }

    const float* Alog = dir ? Alb : Alf;
    float Dv = (dir ? Db : Df)[d];
    float4 al = *(const float4*)&Alog[d*DSTATE + lane*4];
    float a0 = -__expf(al.x), a1 = -__expf(al.y);
    float a2 = -__expf(al.z), a3 = -__expf(al.w);
    const float* dtw = dir ? dtwb : dtwf;
    float dtbias = (dir ? dtbb : dtbf)[d];
    float w0dt = 0.f, w1dt = 0.f, w2dt = 0.f, w3dt = 0.f;
    if (lane < 3) {
        float4 wv = *(const float4*)&dtw[d*DTRANK + lane*4];
        w0dt = wv.x; w1dt = wv.y; w2dt = wv.z; w3dt = wv.w;
    }
    const __half* xcp = g_xc[dir];
    const __half* zp  = g_zs[dir];

    float h0=0.f,h1=0.f,h2=0.f,h3=0.f;
    float p0=1.f,p1=1.f,p2=1.f,p3=1.f;
    float w0=0.f,w1=0.f,w2=0.f,w3=0.f;
    float acc=0.f;
    __syncthreads();

    int r = r0;
    for (int t = 0; t < CHL; t++, r += step) {
        size_t rd = (size_t)r * DIN + d;
        float xcv = __half2float(xcp[rd]);
        float zsv = __half2float(zp[rd]);
        float4 Tv = *(const float4*)&sproj[t][lane*4];
        float4 Bv = *(const float4*)&sproj[t][DTRANK + lane*4];
        float4 Cv = *(const float4*)&sproj[t][DTRANK + DSTATE + lane*4];
        // dt = softplus(proj . dtw + bias), 16-wide dot via 4-lane group
        float dp = fmaf(w3dt, Tv.w, fmaf(w2dt, Tv.z, fmaf(w1dt, Tv.y, w0dt*Tv.x)));
        dp += __shfl_xor_sync(0xffffffffu, dp, 1);
        dp += __shfl_xor_sync(0xffffffffu, dp, 2);
        dp += dtbias;
        float dtv = fmaxf(dp, 0.0f) + __logf(1.0f + __expf(-fabsf(dp)));
        // state update + decay product + influence vector
        float dtx = dtv * xcv;
        float e0 = __expf(dtv*a0), e1 = __expf(dtv*a1);
        float e2 = __expf(dtv*a2), e3 = __expf(dtv*a3);
        h0 = fmaf(e0, h0, dtx*Bv.x);  p0 *= e0;
        h1 = fmaf(e1, h1, dtx*Bv.y);  p1 *= e1;
        h2 = fmaf(e2, h2, dtx*Bv.z);  p2 *= e2;
        h3 = fmaf(e3, h3, dtx*Bv.w);  p3 *= e3;
        float zc0 = zsv*Cv.x, zc1 = zsv*Cv.y, zc2 = zsv*Cv.z, zc3 = zsv*Cv.w;
        w0 = fmaf(zc0, p0, w0); w1 = fmaf(zc1, p1, w1);
        w2 = fmaf(zc2, p2, w2); w3 = fmaf(zc3, p3, w3);
        float part = fmaf(h0,Cv.x, fmaf(h1,Cv.y, fmaf(h2,Cv.z, h3*Cv.w)));
        part += __shfl_xor_sync(0xffffffffu, part, 1);
        part += __shfl_xor_sync(0xffffffffu, part, 2);
        acc = fmaf(fmaf(xcv, Dv, part), zsv, acc);
    }

    int part_i = ((zz*CH + c)*DIN + d);
    g_hout[part_i*4 + lane] = make_float4(h0, h1, h2, h3);
    g_pf  [part_i*4 + lane] = make_float4(p0, p1, p2, p3);
    g_w   [part_i*4 + lane] = make_float4(w0, w1, w2, w3);
    if (lane == 0) g_pacc[part_i] = acc;
}

// ---------------- scan combine: stitch chunks, write ysum -------------------
__global__ __launch_bounds__(256) void scan_combine_kernel() {
    int gid  = (blockIdx.x * 256 + threadIdx.x) >> 2;
    int lane = threadIdx.x & 3;
    if (gid >= 2 * BATCH * DIN) return;
    int zz = gid / DIN;              // dir*BATCH + b
    int d  = gid - zz * DIN;
    float4 hin = make_float4(0.f, 0.f, 0.f, 0.f);
    float acc = 0.f;
    #pragma unroll
    for (int c = 0; c < CH; c++) {
        int part_i = ((zz*CH + c)*DIN + d);
        float4 wv = g_w[part_i*4 + lane];
        float dv = fmaf(wv.w, hin.w, fmaf(wv.z, hin.z, fmaf(wv.y, hin.y, wv.x*hin.x)));
        dv += __shfl_xor_sync(0xffffffffu, dv, 1);
        dv += __shfl_xor_sync(0xffffffffu, dv, 2);
        acc += g_pacc[part_i] + dv;
        float4 ho = g_hout[part_i*4 + lane];
        float4 pf = g_pf[part_i*4 + lane];
        hin.x = fmaf(pf.x, hin.x, ho.x);
        hin.y = fmaf(pf.y, hin.y, ho.y);
        hin.z = fmaf(pf.z, hin.z, ho.z);
        hin.w = fmaf(pf.w, hin.w, ho.w);
    }
    if (lane == 0) {
        int dir = zz / BATCH, b = zz - dir*BATCH;
        g_ysum[dir][b*DIN + d] = acc;
    }
}

// ---------------- head: mean -> out_proj (both dirs) -> fc ------------------
__global__ void head_kernel(const float* __restrict__ fow, const float* __restrict__ bow,
                            const float* __restrict__ fcw, const float* __restrict__ fcb,
                            float* __restrict__ out) {
    int b = blockIdx.x;
    __shared__ float ys0[DIN], ys1[DIN], o[DIMV];
    int t = threadIdx.x;
    for (int i = t; i < DIN; i += DIMV) {
        ys0[i] = g_ysum[0][b*DIN + i] * (1.0f/SEQL);
        ys1[i] = g_ysum[1][b*DIN + i] * (1.0f/SEQL);
    }
    __syncthreads();
    float acc = 0.f;
    #pragma unroll 4
    for (int di = 0; di < DIN; di++)
        acc = fmaf(ys0[di], fow[(size_t)t*DIN + di], fmaf(ys1[di], bow[(size_t)t*DIN + di], acc));
    o[t] = acc;
    __syncthreads();
    if (t < 4) {
        float s = fcb[t];
        #pragma unroll 4
        for (int d = 0; d < DIMV; d++) s = fmaf(o[d], fcw[t*DIMV + d], s);
        out[b*4 + t] = s;
    }
}

// ---------------- launch ----------------------------------------------------
extern "C" void kernel_launch(void* const* d_in, const int* in_sizes, int n_in,
                              void* d_out, int out_size) {
    (void)in_sizes; (void)n_in; (void)out_size;
    const float* x       = (const float*)d_in[0];
    const float* patch_w = (const float*)d_in[1];
    const float* patch_b = (const float*)d_in[2];
    const float* ln_g    = (const float*)d_in[3];
    const float* ln_b    = (const float*)d_in[4];
    const float* fc_w    = (const float*)d_in[5];
    const float* fc_b    = (const float*)d_in[6];
    const float* P[2][9];
    for (int dir = 0; dir < 2; dir++)
        for (int i = 0; i < 9; i++)
            P[dir][i] = (const float*)d_in[7 + dir*9 + i];

    float *tok, *proj;
    __half *xi, *zs, *xc;
    cudaGetSymbolAddress((void**)&tok,  g_tok);
    cudaGetSymbolAddress((void**)&xi,   g_xi);
    cudaGetSymbolAddress((void**)&zs,   g_zs);
    cudaGetSymbolAddress((void**)&xc,   g_xc);
    cudaGetSymbolAddress((void**)&proj, g_proj);

    cudaFuncSetAttribute(gemm_fp16_kernel<true,false,false>,
                         cudaFuncAttributeMaxDynamicSharedMemorySize, GEMM_SMEM);
    cudaFuncSetAttribute(gemm_fp16_kernel<false,false,true>,
                         cudaFuncAttributeMaxDynamicSharedMemorySize, GEMM_SMEM);
    cudaFuncSetAttribute(gemm_fp16_kernel<false,true,false>,
                         cudaFuncAttributeMaxDynamicSharedMemorySize, GEMM_SMEM);

    // 1. patch embed GEMM with implicit im2col (bias folded into LN)
    gemm_fp16_kernel<true,false,false><<<dim3(DIMV/NT, MTOK/MT, 1), 256, GEMM_SMEM>>>(
        x, x, patch_w, patch_w, tok, tok, tok, tok, 768, DIMV, DIMV);
    // 2. layernorm in place (adds patch_b first)
    ln_kernel<<<MTOK/8, 256>>>(tok, patch_b, ln_g, ln_b);
    // 3. in-projection, both dirs; x -> g_xi (half), z -> g_zs (silu, half)
    gemm_fp16_kernel<false,false,true><<<dim3((2*DIN)/NT, MTOK/MT, 2), 256, GEMM_SMEM>>>(
        tok, tok, P[0][0], P[1][0],
        xi, xi + (size_t)MTOK*DIN,
        zs, zs + (size_t)MTOK*DIN, DIMV, 2*DIN, DIN);
    // 4. conv + silu (half -> half)
    conv_silu_kernel<<<dim3(SEQL/8, BATCH, 2), 96>>>(P[0][1], P[0][2], P[1][1], P[1][2]);
    // 5. x-projection (dt_raw | B | C); A half, weights padded 44 -> 64 cols
    gemm_fp16_kernel<false,true,false><<<dim3(1, MTOK/MT, 2), 256, GEMM_SMEM>>>(
        xc, xc + (size_t)MTOK*DIN, P[0][3], P[1][3],
        proj, proj + (size_t)MTOK*NPROJP,
        proj, proj + (size_t)MTOK*NPROJP, DIN, 44, NPROJP);
    // 6. chunked selective scan (dt fused): parts then combine
    scan_part_kernel<<<dim3(DIN/64, CH, 2*BATCH), 256>>>(
        P[0][6], P[0][7], P[1][6], P[1][7],
        P[0][4], P[0][5], P[1][4], P[1][5]);
    scan_combine_kernel<<<(2*BATCH*DIN*4 + 255)/256, 256>>>();
    // 7. head: mean-pool -> out_w (both dirs) -> fc
    head_kernel<<<BATCH, DIMV>>>(P[0][8], P[1][8], fc_w, fc_b, (float*)d_out);
}

// round 13
// speedup vs baseline: 2.3946x; 1.0762x over previous
#include <cuda_runtime.h>
#include <cuda_fp16.h>
#include <mma.h>
#include <cstdint>
#include <cstddef>

using namespace nvcuda;

// ---------------- problem constants ----------------
#define BATCH   32
#define SEQL    576                 // 24*24 tokens
#define MTOK    (BATCH*SEQL)        // 18432
#define DIMV    192
#define DIN     384                 // 2*DIM
#define DSTATE  16
#define DTRANK  12
#define NPROJP  64                  // padded proj row stride (real cols: 44)
#define CH      8                   // scan chunks
#define CHL     (SEQL/CH)           // 72 tokens per chunk

// ---------------- scratch (device globals; no allocation) ----------------
__device__ float  g_tok [(size_t)MTOK * DIMV];            // fp32 (LN in place)
__device__ __half g_xi  [2][(size_t)MTOK * DIN];          // raw x (pre-conv)
__device__ __half g_zs  [2][(size_t)MTOK * DIN];          // silu(z)
__device__ __half g_xc  [2][(size_t)MTOK * DIN];          // silu(conv(x))
__device__ float  g_proj[2][(size_t)MTOK * NPROJP];       // [dt_raw|B|C|pad]
// per-chunk partials: part_i = ((zz*CH+c)*DIN+d), 4 float4 per tensor
#define NPART (2*BATCH*CH*DIN)
__device__ float4 g_hout[(size_t)NPART*4];
__device__ float4 g_pf  [(size_t)NPART*4];
__device__ float4 g_w   [(size_t)NPART*4];
__device__ float  g_pacc[NPART];
__device__ float  g_ysum[2][BATCH * DIN];

// ---------------- fp16 WMMA GEMM -------------------------------------------
#define MT 128
#define NT 64
#define KT 32
#define SBK 40
#define ASZ (MT*SBK)
#define BSZ (NT*SBK)
#define GEMM_SMEM 32768

#define CVTSTOREH(dst, off, v) do {                                           \
    __half2 h0_ = __floats2half2_rn((v).x, (v).y);                            \
    __half2 h1_ = __floats2half2_rn((v).z, (v).w);                            \
    *(__half2*)&(dst)[(off)]     = h0_;                                       \
    *(__half2*)&(dst)[(off) + 2] = h1_;                                       \
} while (0)

template<bool IMC, bool AHALF, bool ZSPLIT>
__global__ __launch_bounds__(256) void gemm_fp16_kernel(
    const void* __restrict__ A0v, const void* __restrict__ A1v,
    const float* __restrict__ W0, const float* __restrict__ W1,
    void* __restrict__ Cx0, void* __restrict__ Cx1,
    void* __restrict__ Cz0, void* __restrict__ Cz1,
    int K, int Nw, int Nout)
{
    extern __shared__ __half sm[];
    __half* As = sm;
    __half* Bs = sm + 2*ASZ;

    const void* Av = blockIdx.z ? A1v : A0v;
    const float* W = blockIdx.z ? W1 : W0;
    void* Cx = blockIdx.z ? Cx1 : Cx0;
    void* Cz = blockIdx.z ? Cz1 : Cz0;

    const int tid  = threadIdx.x;
    const int warp = tid >> 5;
    const int lane = tid & 31;
    const int wm   = warp >> 1;
    const int wn   = warp & 1;
    const int m0 = blockIdx.y * MT;
    const int n0 = blockIdx.x * NT;
    const int ar = tid >> 3, akc = (tid & 7) * 4;

    int rb[4];
    if (IMC) {
        #pragma unroll
        for (int i = 0; i < 4; i++) {
            int tok = m0 + ar + i*32;
            int b = tok / SEQL, rl = tok - b*SEQL;
            int hp = rl / 24, wp = rl - hp*24;
            rb[i] = b*442368 + hp*6144 + wp*16;
        }
    }

    wmma::fragment<wmma::accumulator,16,16,16,float> acc[2][2];
    #pragma unroll
    for (int i = 0; i < 2; i++)
        #pragma unroll
        for (int j = 0; j < 2; j++)
            wmma::fill_fragment(acc[i][j], 0.0f);

    float4 pa[4];
    uint2  pah[4];
    float4 pb[2];

    #define LOADT(k0)  do {                                                   \
        if (IMC) {                                                            \
            const float* Af = (const float*)Av;                               \
            int k_ = (k0) + akc;                                              \
            int c_ = k_ >> 8, pq_ = k_ & 255;                                 \
            int koff_ = c_*147456 + (pq_ >> 4)*384 + (pq_ & 15);              \
            _Pragma("unroll")                                                 \
            for (int i = 0; i < 4; i++)                                       \
                pa[i] = *(const float4*)&Af[rb[i] + koff_];                   \
        } else if (AHALF) {                                                   \
            const __half* Ah = (const __half*)Av;                             \
            _Pragma("unroll")                                                 \
            for (int i = 0; i < 4; i++)                                       \
                pah[i] = *(const uint2*)&Ah[(size_t)(m0 + ar + i*32)*K + (k0) + akc]; \
        } else {                                                              \
            const float* Af = (const float*)Av;                               \
            _Pragma("unroll")                                                 \
            for (int i = 0; i < 4; i++)                                       \
                pa[i] = *(const float4*)&Af[(size_t)(m0 + ar + i*32)*K + (k0) + akc]; \
        }                                                                     \
        _Pragma("unroll")                                                     \
        for (int i = 0; i < 2; i++) {                                         \
            int r_ = ar + i*32;                                               \
            pb[i] = (n0 + r_ < Nw)                                            \
                ? *(const float4*)&W[(size_t)(n0 + r_)*K + (k0) + akc]        \
                : make_float4(0.f,0.f,0.f,0.f);                               \
        }                                                                     \
    } while (0)

    #define STORET(buf)  do {                                                 \
        _Pragma("unroll")                                                     \
        for (int i = 0; i < 4; i++) {                                         \
            int off_ = (buf)*ASZ + (ar + i*32)*SBK + akc;                     \
            if (AHALF) *(uint2*)&As[off_] = pah[i];                           \
            else       CVTSTOREH(As, off_, pa[i]);                            \
        }                                                                     \
        _Pragma("unroll")                                                     \
        for (int i = 0; i < 2; i++)                                           \
            CVTSTOREH(Bs, (buf)*BSZ + (ar + i*32)*SBK + akc, pb[i]);          \
    } while (0)

    LOADT(0);
    STORET(0);
    __syncthreads();

    int buf = 0;
    for (int k0 = 0; k0 < K; k0 += KT) {
        const bool more = (k0 + KT) < K;
        if (more) LOADT(k0 + KT);
        #pragma unroll
        for (int kk = 0; kk < KT; kk += 16) {
            wmma::fragment<wmma::matrix_b,16,16,16,__half,wmma::col_major> bf[2];
            #pragma unroll
            for (int j = 0; j < 2; j++)
                wmma::load_matrix_sync(bf[j], &Bs[buf*BSZ + (wn*32 + j*16)*SBK + kk], SBK);
            #pragma unroll
            for (int i = 0; i < 2; i++) {
                wmma::fragment<wmma::matrix_a,16,16,16,__half,wmma::row_major> af;
                wmma::load_matrix_sync(af, &As[buf*ASZ + (wm*32 + i*16)*SBK + kk], SBK);
                #pragma unroll
                for (int j = 0; j < 2; j++)
                    wmma::mma_sync(acc[i][j], af, bf[j], acc[i][j]);
            }
        }
        if (more) STORET(buf ^ 1);
        __syncthreads();
        buf ^= 1;
    }

    if (ZSPLIT) {
        __syncthreads();
        float* stage = reinterpret_cast<float*>(sm) + warp * 1024;
        #pragma unroll
        for (int i = 0; i < 2; i++)
            #pragma unroll
            for (int j = 0; j < 2; j++)
                wmma::store_matrix_sync(&stage[i*16*32 + j*16], acc[i][j], 32,
                                        wmma::mem_row_major);
        __syncwarp();
        int nbase = n0 + wn*32;
        bool isz = nbase >= DIN;
        __half* Cd = reinterpret_cast<__half*>(isz ? Cz : Cx);
        int nc0 = (isz ? nbase - DIN : nbase) + (lane & 3) * 8;
        #pragma unroll
        for (int r4 = 0; r4 < 4; r4++) {
            int row = r4*8 + (lane >> 2);
            const float* src = &stage[row*32 + (lane & 3)*8];
            __half2 h[4];
            #pragma unroll
            for (int c = 0; c < 4; c++) {
                float v0 = src[c*2], v1 = src[c*2 + 1];
                if (isz) {
                    v0 = v0 * __frcp_rn(1.0f + __expf(-v0));
                    v1 = v1 * __frcp_rn(1.0f + __expf(-v1));
                }
                h[c] = __floats2half2_rn(v0, v1);
            }
            *(uint4*)&Cd[(size_t)(m0 + wm*32 + row)*Nout + nc0] = *(uint4*)h;
        }
    } else {
        float* C = (float*)Cx;
        #pragma unroll
        for (int i = 0; i < 2; i++)
            #pragma unroll
            for (int j = 0; j < 2; j++)
                wmma::store_matrix_sync(
                    &C[(size_t)(m0 + wm*32 + i*16)*Nout + n0 + wn*32 + j*16],
                    acc[i][j], Nout, wmma::mem_row_major);
    }
    #undef LOADT
    #undef STORET
}

// ---------------- LayerNorm over DIM=192 (patch bias folded in) -------------
__global__ void ln_kernel(float* __restrict__ tok, const float* __restrict__ pb,
                          const float* __restrict__ g, const float* __restrict__ b) {
    int row  = blockIdx.x * 8 + (threadIdx.x >> 5);
    int lane = threadIdx.x & 31;
    float* p = tok + (size_t)row * DIMV;
    float v[6]; float s = 0.f;
    #pragma unroll
    for (int i = 0; i < 6; i++) {
        int c = lane + i*32;
        v[i] = p[c] + pb[c];
        s += v[i];
    }
    #pragma unroll
    for (int o = 16; o; o >>= 1) s += __shfl_xor_sync(0xffffffffu, s, o);
    float mu = s * (1.0f/192.0f);
    float q = 0.f;
    #pragma unroll
    for (int i = 0; i < 6; i++) { float d = v[i] - mu; q = fmaf(d, d, q); }
    #pragma unroll
    for (int o = 16; o; o >>= 1) q += __shfl_xor_sync(0xffffffffu, q, o);
    float rstd = rsqrtf(q * (1.0f/192.0f) + 1e-5f);
    #pragma unroll
    for (int i = 0; i < 6; i++) {
        int c = lane + i*32;
        p[c] = (v[i] - mu) * rstd * g[c] + b[c];
    }
}

// ---------------- conv + silu (half in/out, fp32 math) ----------------------
__device__ __forceinline__ float4 h4tof4(uint2 u) {
    float2 a = __half22float2(*(__half2*)&u.x);
    float2 b = __half22float2(*(__half2*)&u.y);
    return make_float4(a.x, a.y, b.x, b.y);
}

__global__ __launch_bounds__(96) void conv_silu_kernel(
    const float* __restrict__ cwf, const float* __restrict__ cbf,
    const float* __restrict__ cwb, const float* __restrict__ cbb)
{
    const int dir = blockIdx.z;
    const int b   = blockIdx.y;
    const int l0  = blockIdx.x * 8;
    const int d   = threadIdx.x * 4;
    const float* cw = dir ? cwb : cwf;
    const float* cb = dir ? cbb : cbf;

    float4 a0 = *(const float4*)&cw[(d+0)*4];
    float4 a1 = *(const float4*)&cw[(d+1)*4];
    float4 a2 = *(const float4*)&cw[(d+2)*4];
    float4 a3 = *(const float4*)&cw[(d+3)*4];
    float4 t0 = make_float4(a0.x, a1.x, a2.x, a3.x);
    float4 t1 = make_float4(a0.y, a1.y, a2.y, a3.y);
    float4 t2 = make_float4(a0.z, a1.z, a2.z, a3.z);
    float4 t3 = make_float4(a0.w, a1.w, a2.w, a3.w);
    float4 bias = *(const float4*)&cb[d];

    const __half* xi = g_xi[dir];
    __half* xc = g_xc[dir];
    const int s  = dir ? -1 : 1;
    int l = dir ? (l0 + 7) : l0;

    #define LDX(ll) ((unsigned)(ll) < SEQL                                     \
        ? h4tof4(*(const uint2*)&xi[((size_t)(b*SEQL + (ll)))*DIN + d])        \
        : make_float4(0.f,0.f,0.f,0.f))

    float4 w0 = LDX(l - 3*s);
    float4 w1 = LDX(l - 2*s);
    float4 w2 = LDX(l - 1*s);

    #pragma unroll
    for (int i = 0; i < 8; i++, l += s) {
        float4 w3 = h4tof4(*(const uint2*)&xi[(size_t)(b*SEQL + l)*DIN + d]);
        float4 r;
        r.x = fmaf(t3.x, w3.x, fmaf(t2.x, w2.x, fmaf(t1.x, w1.x, fmaf(t0.x, w0.x, bias.x))));
        r.y = fmaf(t3.y, w3.y, fmaf(t2.y, w2.y, fmaf(t1.y, w1.y, fmaf(t0.y, w0.y, bias.y))));
        r.z = fmaf(t3.z, w3.z, fmaf(t2.z, w2.z, fmaf(t1.z, w1.z, fmaf(t0.z, w0.z, bias.z))));
        r.w = fmaf(t3.w, w3.w, fmaf(t2.w, w2.w, fmaf(t1.w, w1.w, fmaf(t0.w, w0.w, bias.w))));
        r.x = r.x * __frcp_rn(1.0f + __expf(-r.x));
        r.y = r.y * __frcp_rn(1.0f + __expf(-r.y));
        r.z = r.z * __frcp_rn(1.0f + __expf(-r.z));
        r.w = r.w * __frcp_rn(1.0f + __expf(-r.w));
        uint2 o;
        *(__half2*)&o.x = __floats2half2_rn(r.x, r.y);
        *(__half2*)&o.y = __floats2half2_rn(r.z, r.w);
        *(uint2*)&xc[(size_t)(b*SEQL + l)*DIN + d] = o;
        w0 = w1; w1 = w2; w2 = w3;
    }
    #undef LDX
}

// ---------------- scan part: one THREAD per (dir,b,chunk,d) ------------------
// 16 states in registers; no shfls; sproj rows are warp-uniform (broadcast).
// h_loc, P (cumulative decay), w = sum zs*C*P, acc_local; exact chunking.
__global__ __launch_bounds__(128) void scan_part_kernel(
    const float* __restrict__ Alf, const float* __restrict__ Df,
    const float* __restrict__ Alb, const float* __restrict__ Db,
    const float* __restrict__ dtwf, const float* __restrict__ dtbf,
    const float* __restrict__ dtwb, const float* __restrict__ dtbb)
{
    __shared__ float sproj[CHL][48];
    const int tid  = threadIdx.x;
    const int c    = blockIdx.y;
    const int zz   = blockIdx.z;
    const int dir  = zz / BATCH;
    const int b    = zz - dir*BATCH;
    const int d    = blockIdx.x * 128 + tid;
    const int step = dir ? -1 : 1;
    const int r0   = b*SEQL + (dir ? (SEQL - 1 - c*CHL) : c*CHL);

    // stage proj rows for this chunk in scan order (CHL*12 float4 loads)
    const float* pp = g_proj[dir];
    for (int idx = tid; idx < CHL*12; idx += 128) {
        int row = idx / 12, q = idx - row*12;
        int rr = r0 + step*row;
        *(float4*)&sproj[row][q*4] = *(const float4*)&pp[(size_t)rr*NPROJP + q*4];
    }

    const float* Alog = dir ? Alb : Alf;
    float Dv = (dir ? Db : Df)[d];
    float a[16];
    #pragma unroll
    for (int j = 0; j < 16; j++) a[j] = -__expf(Alog[d*DSTATE + j]);
    const float* dtwp = dir ? dtwb : dtwf;
    float dtbias = (dir ? dtbb : dtbf)[d];
    float dtw[12];
    #pragma unroll
    for (int k = 0; k < 12; k++) dtw[k] = dtwp[d*DTRANK + k];
    const __half* xcp = g_xc[dir];
    const __half* zp  = g_zs[dir];

    float h[16], p[16], w[16];
    #pragma unroll
    for (int j = 0; j < 16; j++) { h[j] = 0.f; p[j] = 1.f; w[j] = 0.f; }
    float acc = 0.f;
    __syncthreads();

    int r = r0;
    for (int t = 0; t < CHL; t++, r += step) {
        size_t rd = (size_t)r * DIN + d;
        float xcv = __half2float(xcp[rd]);
        float zsv = __half2float(zp[rd]);
        const float* row = sproj[t];
        // dt = softplus(dot(row[0:12], dtw) + bias)
        float dp = dtbias;
        #pragma unroll
        for (int k = 0; k < 12; k++) dp = fmaf(row[k], dtw[k], dp);
        float dtv = fmaxf(dp, 0.0f) + __logf(1.0f + __expf(-fabsf(dp)));
        float dtx = dtv * xcv;
        float part = 0.f;
        #pragma unroll
        for (int j = 0; j < 16; j++) {
            float Bj = row[DTRANK + j];
            float Cj = row[DTRANK + DSTATE + j];
            float e  = __expf(dtv * a[j]);
            h[j] = fmaf(e, h[j], dtx * Bj);
            p[j] *= e;
            w[j] = fmaf(zsv * Cj, p[j], w[j]);
            part = fmaf(h[j], Cj, part);
        }
        acc = fmaf(fmaf(xcv, Dv, part), zsv, acc);
    }

    size_t part_i = ((size_t)(zz*CH + c)*DIN + d);
    #pragma unroll
    for (int q = 0; q < 4; q++) {
        g_hout[part_i*4 + q] = make_float4(h[q*4], h[q*4+1], h[q*4+2], h[q*4+3]);
        g_pf  [part_i*4 + q] = make_float4(p[q*4], p[q*4+1], p[q*4+2], p[q*4+3]);
        g_w   [part_i*4 + q] = make_float4(w[q*4], w[q*4+1], w[q*4+2], w[q*4+3]);
    }
    g_pacc[part_i] = acc;
}

// ---------------- scan combine: one thread per (dir,b,d) --------------------
__global__ __launch_bounds__(128) void scan_combine_kernel() {
    int gid = blockIdx.x * 128 + threadIdx.x;
    if (gid >= 2 * BATCH * DIN) return;
    int zz = gid / DIN;
    int d  = gid - zz * DIN;
    float hin[16];
    #pragma unroll
    for (int j = 0; j < 16; j++) hin[j] = 0.f;
    float acc = 0.f;
    #pragma unroll
    for (int c = 0; c < CH; c++) {
        size_t part_i = ((size_t)(zz*CH + c)*DIN + d);
        float dv = 0.f;
        #pragma unroll
        for (int q = 0; q < 4; q++) {
            float4 wv = g_w[part_i*4 + q];
            dv = fmaf(wv.x, hin[q*4+0], dv);
            dv = fmaf(wv.y, hin[q*4+1], dv);
            dv = fmaf(wv.z, hin[q*4+2], dv);
            dv = fmaf(wv.w, hin[q*4+3], dv);
        }
        acc += g_pacc[part_i] + dv;
        #pragma unroll
        for (int q = 0; q < 4; q++) {
            float4 ho = g_hout[part_i*4 + q];
            float4 pf = g_pf[part_i*4 + q];
            hin[q*4+0] = fmaf(pf.x, hin[q*4+0], ho.x);
            hin[q*4+1] = fmaf(pf.y, hin[q*4+1], ho.y);
            hin[q*4+2] = fmaf(pf.z, hin[q*4+2], ho.z);
            hin[q*4+3] = fmaf(pf.w, hin[q*4+3], ho.w);
        }
    }
    int dir = zz / BATCH, b = zz - dir*BATCH;
    g_ysum[dir][b*DIN + d] = acc;
}

// ---------------- head: mean -> out_proj (both dirs) -> fc ------------------
__global__ void head_kernel(const float* __restrict__ fow, const float* __restrict__ bow,
                            const float* __restrict__ fcw, const float* __restrict__ fcb,
                            float* __restrict__ out) {
    int b = blockIdx.x;
    __shared__ float ys0[DIN], ys1[DIN], o[DIMV];
    int t = threadIdx.x;
    for (int i = t; i < DIN; i += DIMV) {
        ys0[i] = g_ysum[0][b*DIN + i] * (1.0f/SEQL);
        ys1[i] = g_ysum[1][b*DIN + i] * (1.0f/SEQL);
    }
    __syncthreads();
    float acc = 0.f;
    #pragma unroll 4
    for (int di = 0; di < DIN; di++)
        acc = fmaf(ys0[di], fow[(size_t)t*DIN + di], fmaf(ys1[di], bow[(size_t)t*DIN + di], acc));
    o[t] = acc;
    __syncthreads();
    if (t < 4) {
        float s = fcb[t];
        #pragma unroll 4
        for (int d = 0; d < DIMV; d++) s = fmaf(o[d], fcw[t*DIMV + d], s);
        out[b*4 + t] = s;
    }
}

// ---------------- launch ----------------------------------------------------
extern "C" void kernel_launch(void* const* d_in, const int* in_sizes, int n_in,
                              void* d_out, int out_size) {
    (void)in_sizes; (void)n_in; (void)out_size;
    const float* x       = (const float*)d_in[0];
    const float* patch_w = (const float*)d_in[1];
    const float* patch_b = (const float*)d_in[2];
    const float* ln_g    = (const float*)d_in[3];
    const float* ln_b    = (const float*)d_in[4];
    const float* fc_w    = (const float*)d_in[5];
    const float* fc_b    = (const float*)d_in[6];
    const float* P[2][9];
    for (int dir = 0; dir < 2; dir++)
        for (int i = 0; i < 9; i++)
            P[dir][i] = (const float*)d_in[7 + dir*9 + i];

    float *tok, *proj;
    __half *xi, *zs, *xc;
    cudaGetSymbolAddress((void**)&tok,  g_tok);
    cudaGetSymbolAddress((void**)&xi,   g_xi);
    cudaGetSymbolAddress((void**)&zs,   g_zs);
    cudaGetSymbolAddress((void**)&xc,   g_xc);
    cudaGetSymbolAddress((void**)&proj, g_proj);

    cudaFuncSetAttribute(gemm_fp16_kernel<true,false,false>,
                         cudaFuncAttributeMaxDynamicSharedMemorySize, GEMM_SMEM);
    cudaFuncSetAttribute(gemm_fp16_kernel<false,false,true>,
                         cudaFuncAttributeMaxDynamicSharedMemorySize, GEMM_SMEM);
    cudaFuncSetAttribute(gemm_fp16_kernel<false,true,false>,
                         cudaFuncAttributeMaxDynamicSharedMemorySize, GEMM_SMEM);

    // 1. patch embed GEMM with implicit im2col (bias folded into LN)
    gemm_fp16_kernel<true,false,false><<<dim3(DIMV/NT, MTOK/MT, 1), 256, GEMM_SMEM>>>(
        x, x, patch_w, patch_w, tok, tok, tok, tok, 768, DIMV, DIMV);
    // 2. layernorm in place (adds patch_b first)
    ln_kernel<<<MTOK/8, 256>>>(tok, patch_b, ln_g, ln_b);
    // 3. in-projection, both dirs; x -> g_xi (half), z -> g_zs (silu, half)
    gemm_fp16_kernel<false,false,true><<<dim3((2*DIN)/NT, MTOK/MT, 2), 256, GEMM_SMEM>>>(
        tok, tok, P[0][0], P[1][0],
        xi, xi + (size_t)MTOK*DIN,
        zs, zs + (size_t)MTOK*DIN, DIMV, 2*DIN, DIN);
    // 4. conv + silu (half -> half)
    conv_silu_kernel<<<dim3(SEQL/8, BATCH, 2), 96>>>(P[0][1], P[0][2], P[1][1], P[1][2]);
    // 5. x-projection (dt_raw | B | C); A half, weights padded 44 -> 64 cols
    gemm_fp16_kernel<false,true,false><<<dim3(1, MTOK/MT, 2), 256, GEMM_SMEM>>>(
        xc, xc + (size_t)MTOK*DIN, P[0][3], P[1][3],
        proj, proj + (size_t)MTOK*NPROJP,
        proj, proj + (size_t)MTOK*NPROJP, DIN, 44, NPROJP);
    // 6. chunked selective scan (dt fused): parts then combine
    scan_part_kernel<<<dim3(DIN/128, CH, 2*BATCH), 128>>>(
        P[0][6], P[0][7], P[1][6], P[1][7],
        P[0][4], P[0][5], P[1][4], P[1][5]);
    scan_combine_kernel<<<(2*BATCH*DIN + 127)/128, 128>>>();
    // 7. head: mean-pool -> out_w (both dirs) -> fc
    head_kernel<<<BATCH, DIMV>>>(P[0][8], P[1][8], fc_w, fc_b, (float*)d_out);
}